// round 1
// baseline (speedup 1.0000x reference)
#include <cuda_runtime.h>
#include <cuda_bf16.h>
#include <math.h>

#define D_MODEL   1024
#define NUM_HEADS 16
#define HEAD_DIM  64
#define BATCH     2
#define SEQ       2048
#define TOKENS    (BATCH * SEQ)      // 4096

// ---------------- scratch (device globals; no allocation allowed) ----------
__device__ float g_qkv[TOKENS * 3 * D_MODEL];                 // 50 MB
__device__ float g_q[BATCH * NUM_HEADS * SEQ * HEAD_DIM];     // 16.8 MB
__device__ float g_k[BATCH * NUM_HEADS * SEQ * HEAD_DIM];
__device__ float g_v[BATCH * NUM_HEADS * SEQ * HEAD_DIM];
__device__ float g_ct[SEQ * 32];
__device__ float g_st[SEQ * 32];
__device__ float g_attn[TOKENS * D_MODEL];                    // 16.8 MB

// ---------------------------------------------------------------------------
// NT GEMM: C[M,N] = A[M,K] * B[N,K]^T  (both row-major, K-major dot products)
// 128x128 tile, BK=8, 256 threads, 8x8 micro-tile.
// ---------------------------------------------------------------------------
__global__ __launch_bounds__(256) void gemm_nt(
    const float* __restrict__ A, const float* __restrict__ B,
    float* __restrict__ C, int M, int N, int K)
{
    __shared__ float As[8][136];   // [k][m], stride 136 => conflict-free compute reads
    __shared__ float Bs[8][136];   // [k][n]

    const int tid = threadIdx.x;
    const int tx  = tid & 15;
    const int ty  = tid >> 4;
    const int m0  = blockIdx.y << 7;
    const int n0  = blockIdx.x << 7;

    const int lr = tid >> 1;          // 0..127: row within tile
    const int lk = (tid & 1) << 2;    // 0 or 4: k offset

    const float* Ap = A + (size_t)(m0 + lr) * K + lk;
    const float* Bp = B + (size_t)(n0 + lr) * K + lk;

    float acc[8][8];
#pragma unroll
    for (int i = 0; i < 8; i++)
#pragma unroll
        for (int j = 0; j < 8; j++) acc[i][j] = 0.0f;

    for (int k0 = 0; k0 < K; k0 += 8) {
        float4 av = *(const float4*)(Ap + k0);
        float4 bv = *(const float4*)(Bp + k0);
        __syncthreads();   // previous compute phase must be done before overwrite
        As[lk + 0][lr] = av.x; As[lk + 1][lr] = av.y;
        As[lk + 2][lr] = av.z; As[lk + 3][lr] = av.w;
        Bs[lk + 0][lr] = bv.x; Bs[lk + 1][lr] = bv.y;
        Bs[lk + 2][lr] = bv.z; Bs[lk + 3][lr] = bv.w;
        __syncthreads();

#pragma unroll
        for (int kk = 0; kk < 8; kk++) {
            float a[8], b[8];
            *(float4*)(a)     = *(const float4*)&As[kk][ty * 4];
            *(float4*)(a + 4) = *(const float4*)&As[kk][ty * 4 + 64];
            *(float4*)(b)     = *(const float4*)&Bs[kk][tx * 4];
            *(float4*)(b + 4) = *(const float4*)&Bs[kk][tx * 4 + 64];
#pragma unroll
            for (int i = 0; i < 8; i++)
#pragma unroll
                for (int j = 0; j < 8; j++)
                    acc[i][j] = fmaf(a[i], b[j], acc[i][j]);
        }
    }

#pragma unroll
    for (int ih = 0; ih < 2; ih++)
#pragma unroll
        for (int i = 0; i < 4; i++) {
            int ii = ih * 4 + i;
            int r  = m0 + ih * 64 + ty * 4 + i;
            float* Cp = C + (size_t)r * N + n0;
            *(float4*)(Cp + tx * 4) =
                make_float4(acc[ii][0], acc[ii][1], acc[ii][2], acc[ii][3]);
            *(float4*)(Cp + 64 + tx * 4) =
                make_float4(acc[ii][4], acc[ii][5], acc[ii][6], acc[ii][7]);
        }
}

// ---------------------------------------------------------------------------
// RoPE tables (fp64 trig to match jax fp32 within tolerance)
// ---------------------------------------------------------------------------
__global__ void rope_table_kernel(const int* __restrict__ pos)
{
    int idx = blockIdx.x * 256 + threadIdx.x;
    if (idx >= SEQ * 32) return;
    int s = idx >> 5, i = idx & 31;
    double f = (double)pos[s] * pow(10000.0, -(double)i / 32.0);
    g_ct[idx] = (float)cos(f);
    g_st[idx] = (float)sin(f);
}

// Split QKV, apply RoPE to Q/K, transpose to [B,H,S,hd]
__global__ __launch_bounds__(256) void rope_split_kernel()
{
    int idx = blockIdx.x * 256 + threadIdx.x;   // TOKENS * 16 * 32 threads
    int i = idx & 31;
    int h = (idx >> 5) & 15;
    int t = idx >> 9;                           // token 0..4095
    int s = t & (SEQ - 1);
    int b = t >> 11;

    const float2* base = (const float2*)(g_qkv + (size_t)t * 3 * D_MODEL);
    float2 q2 = base[(h * 64 + 2 * i) >> 1];
    float2 k2 = base[(D_MODEL + h * 64 + 2 * i) >> 1];
    float2 v2 = base[(2 * D_MODEL + h * 64 + 2 * i) >> 1];

    float c  = g_ct[s * 32 + i];
    float sn = g_st[s * 32 + i];
    float2 qo = make_float2(q2.x * c - q2.y * sn, q2.y * c + q2.x * sn);
    float2 ko = make_float2(k2.x * c - k2.y * sn, k2.y * c + k2.x * sn);

    size_t off = (((size_t)b * NUM_HEADS + h) * SEQ + s) * HEAD_DIM + 2 * i;
    *(float2*)(g_q + off) = qo;
    *(float2*)(g_k + off) = ko;
    *(float2*)(g_v + off) = v2;
}

// ---------------------------------------------------------------------------
// Flash attention (causal). One block = 64 q-rows of one (b,h).
// 256 threads as 16x16; 4x4 micro-tiles. XOR-swizzled smem for transposed
// operands so all compute-phase LDS.128 are bank-conflict-free.
// ---------------------------------------------------------------------------
__device__ __forceinline__ int swz(int r, int c)
{
    // 64-wide row r, logical column c -> physical offset (granule-of-4 XOR swizzle)
    return r * 64 + ((((c >> 2) ^ (r >> 2)) & 15) << 2) + (c & 3);
}

__global__ __launch_bounds__(256) void flash_attn_kernel(float* __restrict__ O)
{
    extern __shared__ float sm[];
    float* Qs = sm;            // [d][row]   swizzled
    float* Ks = sm + 4096;     // [d][col]   swizzled
    float* Vs = sm + 8192;     // [k][dim]   plain
    float* Ps = sm + 12288;    // [k][row]   swizzled

    const int tid = threadIdx.x;
    const int tx  = tid & 15;
    const int ty  = tid >> 4;
    const int qt  = blockIdx.x;   // q tile (32)
    const int h   = blockIdx.y;
    const int b   = blockIdx.z;

    const size_t bh = ((size_t)b * NUM_HEADS + h) * SEQ * HEAD_DIM;
    const float* Qg = g_q + bh + (size_t)qt * 64 * 64;

    // Load Q tile transposed+swizzled
#pragma unroll
    for (int it = 0; it < 4; it++) {
        int idx = it * 256 + tid;
        int row = idx >> 4;
        int d   = (idx & 15) << 2;
        float4 v4 = *(const float4*)(Qg + row * 64 + d);
        Qs[swz(d + 0, row)] = v4.x;
        Qs[swz(d + 1, row)] = v4.y;
        Qs[swz(d + 2, row)] = v4.z;
        Qs[swz(d + 3, row)] = v4.w;
    }

    float m_i[4], l_i[4], o[4][4];
#pragma unroll
    for (int i = 0; i < 4; i++) {
        m_i[i] = -1e30f; l_i[i] = 0.0f;
#pragma unroll
        for (int j = 0; j < 4; j++) o[i][j] = 0.0f;
    }
    __syncthreads();

    for (int jt = 0; jt <= qt; jt++) {
        const float* Kg = g_k + bh + (size_t)jt * 64 * 64;
        const float* Vg = g_v + bh + (size_t)jt * 64 * 64;
#pragma unroll
        for (int it = 0; it < 4; it++) {
            int idx = it * 256 + tid;
            int row = idx >> 4;
            int d   = (idx & 15) << 2;
            float4 kv = *(const float4*)(Kg + row * 64 + d);
            Ks[swz(d + 0, row)] = kv.x;
            Ks[swz(d + 1, row)] = kv.y;
            Ks[swz(d + 2, row)] = kv.z;
            Ks[swz(d + 3, row)] = kv.w;
            *(float4*)&Vs[row * 64 + d] = *(const float4*)(Vg + row * 64 + d);
        }
        __syncthreads();

        // S = Q K^T  (scores)
        float s[4][4];
#pragma unroll
        for (int i = 0; i < 4; i++)
#pragma unroll
            for (int j = 0; j < 4; j++) s[i][j] = 0.0f;

#pragma unroll
        for (int d = 0; d < 64; d++) {
            float4 q4 = *(const float4*)&Qs[d * 64 + (((ty ^ (d >> 2)) & 15) << 2)];
            float4 k4 = *(const float4*)&Ks[d * 64 + (((tx ^ (d >> 2)) & 15) << 2)];
            float qa[4] = {q4.x, q4.y, q4.z, q4.w};
            float ka[4] = {k4.x, k4.y, k4.z, k4.w};
#pragma unroll
            for (int i = 0; i < 4; i++)
#pragma unroll
                for (int j = 0; j < 4; j++)
                    s[i][j] = fmaf(qa[i], ka[j], s[i][j]);
        }

        const float scale = 0.125f;   // 64^-0.5
        if (jt == qt) {
#pragma unroll
            for (int i = 0; i < 4; i++)
#pragma unroll
                for (int j = 0; j < 4; j++) {
                    int qr = ty * 4 + i, kc = tx * 4 + j;
                    s[i][j] = (kc <= qr) ? s[i][j] * scale : -1e30f;
                }
        } else {
#pragma unroll
            for (int i = 0; i < 4; i++)
#pragma unroll
                for (int j = 0; j < 4; j++) s[i][j] *= scale;
        }

        // online softmax over each row (16 lanes share a row)
#pragma unroll
        for (int i = 0; i < 4; i++) {
            float mx = fmaxf(fmaxf(s[i][0], s[i][1]), fmaxf(s[i][2], s[i][3]));
#pragma unroll
            for (int off = 8; off >= 1; off >>= 1)
                mx = fmaxf(mx, __shfl_xor_sync(0xffffffffu, mx, off));
            float mn = fmaxf(m_i[i], mx);
            float alpha = __expf(m_i[i] - mn);
            m_i[i] = mn;
            float rs = 0.0f;
#pragma unroll
            for (int j = 0; j < 4; j++) {
                float p = __expf(s[i][j] - mn);
                s[i][j] = p;
                rs += p;
            }
#pragma unroll
            for (int off = 8; off >= 1; off >>= 1)
                rs += __shfl_xor_sync(0xffffffffu, rs, off);
            l_i[i] = l_i[i] * alpha + rs;
#pragma unroll
            for (int j = 0; j < 4; j++) o[i][j] *= alpha;
        }

        // write P to smem (transposed [k][row], swizzled)
#pragma unroll
        for (int i = 0; i < 4; i++)
#pragma unroll
            for (int j = 0; j < 4; j++)
                Ps[swz(tx * 4 + j, ty * 4 + i)] = s[i][j];
        __syncthreads();

        // O += P V
#pragma unroll
        for (int kk = 0; kk < 64; kk++) {
            float4 p4 = *(const float4*)&Ps[kk * 64 + (((ty ^ (kk >> 2)) & 15) << 2)];
            float4 v4 = *(const float4*)&Vs[kk * 64 + tx * 4];
            float pa[4] = {p4.x, p4.y, p4.z, p4.w};
            float va[4] = {v4.x, v4.y, v4.z, v4.w};
#pragma unroll
            for (int i = 0; i < 4; i++)
#pragma unroll
                for (int j = 0; j < 4; j++)
                    o[i][j] = fmaf(pa[i], va[j], o[i][j]);
        }
        __syncthreads();
    }

    // epilogue: normalize, write back into [B,S,H*hd] token-major layout
#pragma unroll
    for (int i = 0; i < 4; i++) {
        float inv = 1.0f / l_i[i];
        int row = qt * 64 + ty * 4 + i;
        float* Op = O + ((size_t)(b * SEQ + row) * D_MODEL) + h * 64 + tx * 4;
        *(float4*)Op = make_float4(o[i][0] * inv, o[i][1] * inv,
                                   o[i][2] * inv, o[i][3] * inv);
    }
}

// ---------------------------------------------------------------------------
extern "C" void kernel_launch(void* const* d_in, const int* in_sizes, int n_in,
                              void* d_out, int out_size)
{
    (void)in_sizes; (void)n_in; (void)out_size;
    const float* x      = (const float*)d_in[0];
    const float* w_qkv  = (const float*)d_in[1];
    const float* w_o    = (const float*)d_in[2];
    const int*   pos    = (const int*)d_in[3];
    float*       out    = (float*)d_out;

    float *qkv, *attn;
    cudaGetSymbolAddress((void**)&qkv,  g_qkv);
    cudaGetSymbolAddress((void**)&attn, g_attn);

    cudaFuncSetAttribute(flash_attn_kernel,
                         cudaFuncAttributeMaxDynamicSharedMemorySize, 65536);

    rope_table_kernel<<<(SEQ * 32 + 255) / 256, 256>>>(pos);

    // QKV projection: [4096,1024] @ [3072,1024]^T -> [4096,3072]
    gemm_nt<<<dim3(3 * D_MODEL / 128, TOKENS / 128), 256>>>(
        x, w_qkv, qkv, TOKENS, 3 * D_MODEL, D_MODEL);

    rope_split_kernel<<<TOKENS * NUM_HEADS * 32 / 256, 256>>>();

    flash_attn_kernel<<<dim3(SEQ / 64, NUM_HEADS, BATCH), 256, 65536>>>(attn);

    // Output projection: [4096,1024] @ [1024,1024]^T -> [4096,1024]
    gemm_nt<<<dim3(D_MODEL / 128, TOKENS / 128), 256>>>(
        attn, w_o, out, TOKENS, D_MODEL, D_MODEL);
}

// round 4
// speedup vs baseline: 3.7466x; 3.7466x over previous
#include <cuda_runtime.h>
#include <cuda_fp16.h>
#include <math.h>
#include <stdint.h>

#define D_MODEL   1024
#define NUM_HEADS 16
#define HEAD_DIM  64
#define BATCH     2
#define SEQ       2048
#define TOKENS    (BATCH * SEQ)      // 4096

// ---------------- scratch (device globals; no allocation allowed) ----------
__device__ __align__(16) __half g_qkvh[TOKENS * 3 * D_MODEL];   // fp16 qkv
__device__ __align__(16) __half g_qh[TOKENS * D_MODEL];         // [b,h,s,d]
__device__ __align__(16) __half g_kh[TOKENS * D_MODEL];
__device__ __align__(16) __half g_vh[TOKENS * D_MODEL];
__device__ __align__(16) float  g_ct[SEQ * 32];
__device__ __align__(16) float  g_st[SEQ * 32];
__device__ __align__(16) __half g_xh[TOKENS * D_MODEL];
__device__ __align__(16) __half g_xl[TOKENS * D_MODEL];
__device__ __align__(16) __half g_wqh[3 * D_MODEL * D_MODEL];
__device__ __align__(16) __half g_wql[3 * D_MODEL * D_MODEL];
__device__ __align__(16) __half g_woh[D_MODEL * D_MODEL];
__device__ __align__(16) __half g_wol[D_MODEL * D_MODEL];
__device__ __align__(16) __half g_aoh[TOKENS * D_MODEL];
__device__ __align__(16) __half g_aol[TOKENS * D_MODEL];

// ---------------------------------------------------------------------------
// helpers
// ---------------------------------------------------------------------------
__device__ __forceinline__ uint32_t smem_u32(const void* p) {
    uint32_t a;
    asm("{ .reg .u64 t; cvta.to.shared.u64 t, %1; cvt.u32.u64 %0, t; }" : "=r"(a) : "l"(p));
    return a;
}
__device__ __forceinline__ void cp16(uint32_t dst, const void* src) {
    asm volatile("cp.async.cg.shared.global [%0], [%1], 16;" :: "r"(dst), "l"(src));
}
#define CP_COMMIT() asm volatile("cp.async.commit_group;")
#define CP_WAIT(n)  asm volatile("cp.async.wait_group %0;" :: "n"(n))

__device__ __forceinline__ void ldsm4(uint32_t* r, uint32_t a) {
    asm volatile("ldmatrix.sync.aligned.m8n8.x4.shared.b16 {%0,%1,%2,%3}, [%4];"
                 : "=r"(r[0]), "=r"(r[1]), "=r"(r[2]), "=r"(r[3]) : "r"(a));
}
__device__ __forceinline__ void ldsm4t(uint32_t* r, uint32_t a) {
    asm volatile("ldmatrix.sync.aligned.m8n8.x4.trans.shared.b16 {%0,%1,%2,%3}, [%4];"
                 : "=r"(r[0]), "=r"(r[1]), "=r"(r[2]), "=r"(r[3]) : "r"(a));
}
__device__ __forceinline__ void mma_(float* c, const uint32_t* a, const uint32_t* b) {
    asm volatile(
        "mma.sync.aligned.m16n8k16.row.col.f32.f16.f16.f32 "
        "{%0,%1,%2,%3}, {%4,%5,%6,%7}, {%8,%9}, {%0,%1,%2,%3};"
        : "+f"(c[0]), "+f"(c[1]), "+f"(c[2]), "+f"(c[3])
        : "r"(a[0]), "r"(a[1]), "r"(a[2]), "r"(a[3]), "r"(b[0]), "r"(b[1]));
}
__device__ __forceinline__ uint32_t swz(uint32_t o) { return o ^ ((o >> 3) & 0x70); }
__device__ __forceinline__ float ex2(float x) {
    float r; asm("ex2.approx.ftz.f32 %0, %1;" : "=f"(r) : "f"(x)); return r;
}
__device__ __forceinline__ uint32_t packh2(float a, float b) {
    __half2 h = __floats2half2_rn(a, b);
    return *(uint32_t*)&h;
}

// ---------------------------------------------------------------------------
// fp32 -> (fp16 hi, fp16 lo) split
// ---------------------------------------------------------------------------
__global__ __launch_bounds__(256) void split_kernel(
    const float* __restrict__ in, __half* __restrict__ hi,
    __half* __restrict__ lo, int n4)
{
    int i = blockIdx.x * 256 + threadIdx.x;
    if (i >= n4) return;
    float4 v = ((const float4*)in)[i];
    __half hx = __float2half_rn(v.x), hy = __float2half_rn(v.y);
    __half hz = __float2half_rn(v.z), hw = __float2half_rn(v.w);
    __half2* h2 = (__half2*)hi;
    __half2* l2 = (__half2*)lo;
    h2[2 * i]     = __half2(hx, hy);
    h2[2 * i + 1] = __half2(hz, hw);
    l2[2 * i]     = __half2(__float2half_rn(v.x - __half2float(hx)),
                            __float2half_rn(v.y - __half2float(hy)));
    l2[2 * i + 1] = __half2(__float2half_rn(v.z - __half2float(hz)),
                            __float2half_rn(v.w - __half2float(hw)));
}

// ---------------------------------------------------------------------------
// HMMA split-fp16 NT GEMM: C[M,N] = A[M,K] B[N,K]^T, K=1024
// 128x128 tile, BK=64, 256 threads (8 warps, 32x64 warp tile), cp.async x2.
// 3 terms: Ah*Bh + Al*Bh + Ah*Bl  (fp32 accum)
// ---------------------------------------------------------------------------
#define GK 1024
#define STAGE 65536   // Ah 16K | Al 16K | Bh 16K | Bl 16K

__device__ __forceinline__ void gemm_load_stage(
    uint32_t base, int tid, int m0, int n0, int c0,
    const __half* Ah, const __half* Al, const __half* Bh, const __half* Bl)
{
#pragma unroll
    for (int u = 0; u < 4; u++) {
        int idx = u * 256 + tid;          // 0..1023
        int row = idx >> 3, seg = idx & 7;
        uint32_t d = swz((row << 7) + (seg << 4));
        size_t ao = (size_t)(m0 + row) * GK + c0 + seg * 8;
        size_t bo = (size_t)(n0 + row) * GK + c0 + seg * 8;
        cp16(base + d,         Ah + ao);
        cp16(base + 16384 + d, Al + ao);
        cp16(base + 32768 + d, Bh + bo);
        cp16(base + 49152 + d, Bl + bo);
    }
}

template<bool HOUT>
__global__ __launch_bounds__(256, 1) void gemm_tc(
    const __half* __restrict__ Ah, const __half* __restrict__ Al,
    const __half* __restrict__ Bh, const __half* __restrict__ Bl,
    void* __restrict__ Cout, int N)
{
    extern __shared__ char smraw[];
    const uint32_t sb = smem_u32(smraw);
    const int tid = threadIdx.x;
    const int wid = tid >> 5, lane = tid & 31;
    const int wm = wid & 3, wn = wid >> 2;
    const int m0 = blockIdx.y << 7, n0 = blockIdx.x << 7;

    float acc[2][8][4];
#pragma unroll
    for (int f = 0; f < 2; f++)
#pragma unroll
        for (int j = 0; j < 8; j++)
#pragma unroll
            for (int x = 0; x < 4; x++) acc[f][j][x] = 0.0f;

    gemm_load_stage(sb, tid, m0, n0, 0, Ah, Al, Bh, Bl);
    CP_COMMIT();

    for (int c = 0; c < 16; c++) {
        const int buf = c & 1;
        if (c < 15) {
            gemm_load_stage(sb + (buf ^ 1) * STAGE, tid, m0, n0, (c + 1) * 64,
                            Ah, Al, Bh, Bl);
            CP_COMMIT();
            CP_WAIT(1);
        } else {
            CP_WAIT(0);
        }
        __syncthreads();
        const uint32_t base = sb + buf * STAGE;

#pragma unroll
        for (int kt = 0; kt < 4; kt++) {
            uint32_t ah[2][4], al[2][4];
#pragma unroll
            for (int f = 0; f < 2; f++) {
                int mrow = wm * 32 + f * 16 + (lane & 7) + ((lane >> 3) & 1) * 8;
                uint32_t ad = base + swz((mrow << 7) + kt * 32 + ((lane >> 4) << 4));
                ldsm4(ah[f], ad);
                ldsm4(al[f], ad + 16384);
            }
            uint32_t bh[8][2], bl[8][2];
#pragma unroll
            for (int f = 0; f < 4; f++) {
                int nrow = wn * 64 + f * 16 + (lane & 7) + ((lane >> 4) & 1) * 8;
                uint32_t bd = base + 32768 +
                              swz((nrow << 7) + kt * 32 + (((lane >> 3) & 1) << 4));
                uint32_t r[4];
                ldsm4(r, bd);
                bh[2 * f][0] = r[0]; bh[2 * f][1] = r[1];
                bh[2 * f + 1][0] = r[2]; bh[2 * f + 1][1] = r[3];
                ldsm4(r, bd + 16384);
                bl[2 * f][0] = r[0]; bl[2 * f][1] = r[1];
                bl[2 * f + 1][0] = r[2]; bl[2 * f + 1][1] = r[3];
            }
#pragma unroll
            for (int f = 0; f < 2; f++)
#pragma unroll
                for (int j = 0; j < 8; j++) {
                    mma_(acc[f][j], ah[f], bh[j]);
                    mma_(acc[f][j], al[f], bh[j]);
                    mma_(acc[f][j], ah[f], bl[j]);
                }
        }
        __syncthreads();
    }

    // epilogue
    const int g = lane >> 2, i2 = (lane & 3) * 2;
#pragma unroll
    for (int f = 0; f < 2; f++)
#pragma unroll
        for (int j = 0; j < 8; j++) {
            int row = m0 + wm * 32 + f * 16 + g;
            int col = n0 + wn * 64 + j * 8 + i2;
            if (HOUT) {
                __half* C = (__half*)Cout;
                *(__half2*)&C[(size_t)row * N + col] =
                    __floats2half2_rn(acc[f][j][0], acc[f][j][1]);
                *(__half2*)&C[(size_t)(row + 8) * N + col] =
                    __floats2half2_rn(acc[f][j][2], acc[f][j][3]);
            } else {
                float* C = (float*)Cout;
                *(float2*)&C[(size_t)row * N + col] =
                    make_float2(acc[f][j][0], acc[f][j][1]);
                *(float2*)&C[(size_t)(row + 8) * N + col] =
                    make_float2(acc[f][j][2], acc[f][j][3]);
            }
        }
}

// ---------------------------------------------------------------------------
// RoPE tables (fp64 trig)
// ---------------------------------------------------------------------------
__global__ void rope_table_kernel(const int* __restrict__ pos)
{
    int idx = blockIdx.x * 256 + threadIdx.x;
    if (idx >= SEQ * 32) return;
    int s = idx >> 5, i = idx & 31;
    double f = (double)pos[s] * pow(10000.0, -(double)i / 32.0);
    g_ct[idx] = (float)cos(f);
    g_st[idx] = (float)sin(f);
}

// Split fp16 QKV, apply RoPE to Q/K (fp32 math), transpose to [B,H,S,hd] fp16
__global__ __launch_bounds__(256) void rope_split_kernel()
{
    int idx = blockIdx.x * 256 + threadIdx.x;   // TOKENS*16*32
    int i = idx & 31;
    int h = (idx >> 5) & 15;
    int t = idx >> 9;
    int s = t & (SEQ - 1);
    int b = t >> 11;

    const __half2* base = (const __half2*)(g_qkvh + (size_t)t * 3 * D_MODEL);
    float2 q2 = __half22float2(base[(h * 64 + 2 * i) >> 1]);
    float2 k2 = __half22float2(base[(D_MODEL + h * 64 + 2 * i) >> 1]);
    __half2 v2 = base[(2 * D_MODEL + h * 64 + 2 * i) >> 1];

    float c  = g_ct[s * 32 + i];
    float sn = g_st[s * 32 + i];
    float2 qo = make_float2(q2.x * c - q2.y * sn, q2.y * c + q2.x * sn);
    float2 ko = make_float2(k2.x * c - k2.y * sn, k2.y * c + k2.x * sn);

    size_t off = ((((size_t)b * NUM_HEADS + h) * SEQ + s) * HEAD_DIM + 2 * i) >> 1;
    ((__half2*)g_qh)[off] = __floats2half2_rn(qo.x, qo.y);
    ((__half2*)g_kh)[off] = __floats2half2_rn(ko.x, ko.y);
    ((__half2*)g_vh)[off] = v2;
}

// ---------------------------------------------------------------------------
// Flash attention (causal) with HMMA. Block = 128 q rows of one (b,h).
// 8 warps, warp = 16 q rows. K-chunk = 128 keys, cp.async double buffered.
// smem: Q @0 (16K) | K stages @16384 (2x16K) | V stages @49152 (2x16K)
// ---------------------------------------------------------------------------
__device__ __forceinline__ void flash_load_kv(
    uint32_t sb, int tid, int buf, const __half* K0, const __half* V0)
{
#pragma unroll
    for (int u = 0; u < 4; u++) {
        int idx = u * 256 + tid;
        int row = idx >> 3, seg = idx & 7;
        uint32_t d = swz((row << 7) + (seg << 4));
        cp16(sb + 16384 + buf * 16384 + d, K0 + row * 64 + seg * 8);
        cp16(sb + 49152 + buf * 16384 + d, V0 + row * 64 + seg * 8);
    }
}

__global__ __launch_bounds__(256, 1) void flash_attn_tc()
{
    extern __shared__ char smraw[];
    const uint32_t sb = smem_u32(smraw);
    const int tid = threadIdx.x;
    const int wid = tid >> 5, lane = tid & 31;
    const int qt = (int)gridDim.x - 1 - (int)blockIdx.x;   // heavy tiles first
    const int h = blockIdx.y, b = blockIdx.z;

    const size_t bh = ((size_t)b * NUM_HEADS + h) * SEQ * HEAD_DIM;
    const __half* Qg = g_qh + bh + (size_t)qt * 128 * 64;
    const __half* Kg = g_kh + bh;
    const __half* Vg = g_vh + bh;

    // Q tile load
#pragma unroll
    for (int u = 0; u < 4; u++) {
        int idx = u * 256 + tid;
        int row = idx >> 3, seg = idx & 7;
        cp16(sb + swz((row << 7) + (seg << 4)), Qg + row * 64 + seg * 8);
    }
    CP_COMMIT();
    flash_load_kv(sb, tid, 0, Kg, Vg);
    CP_COMMIT();
    CP_WAIT(1);               // Q ready
    __syncthreads();

    // hoist Q fragments
    uint32_t qa[4][4];
#pragma unroll
    for (int kt = 0; kt < 4; kt++) {
        int mrow = wid * 16 + (lane & 7) + ((lane >> 3) & 1) * 8;
        ldsm4(qa[kt], sb + swz((mrow << 7) + kt * 32 + ((lane >> 4) << 4)));
    }

    float oacc[8][4];
#pragma unroll
    for (int j = 0; j < 8; j++)
#pragma unroll
        for (int x = 0; x < 4; x++) oacc[j][x] = 0.0f;
    float m0r = -1e30f, m1r = -1e30f, l0 = 0.0f, l1 = 0.0f;
    const float cs = 0.125f * 1.44269504f;   // scale * log2(e)
    const int g = lane >> 2, i2 = (lane & 3) * 2;

    for (int jt = 0; jt <= qt; jt++) {
        const int buf = jt & 1;
        if (jt < qt) {
            flash_load_kv(sb, tid, buf ^ 1,
                          Kg + (size_t)(jt + 1) * 128 * 64,
                          Vg + (size_t)(jt + 1) * 128 * 64);
            CP_COMMIT();
            CP_WAIT(1);
        } else {
            CP_WAIT(0);
        }
        __syncthreads();
        const uint32_t Kb = sb + 16384 + buf * 16384;
        const uint32_t Vb = sb + 49152 + buf * 16384;

        // S = Q K^T  (m16 x n128 per warp)
        float sacc[16][4];
#pragma unroll
        for (int j = 0; j < 16; j++)
#pragma unroll
            for (int x = 0; x < 4; x++) sacc[j][x] = 0.0f;

#pragma unroll
        for (int kt = 0; kt < 4; kt++) {
            uint32_t kb[16][2];
#pragma unroll
            for (int f = 0; f < 8; f++) {
                int nrow = f * 16 + (lane & 7) + ((lane >> 4) & 1) * 8;
                uint32_t bd = Kb + swz((nrow << 7) + kt * 32 + (((lane >> 3) & 1) << 4));
                uint32_t r[4];
                ldsm4(r, bd);
                kb[2 * f][0] = r[0]; kb[2 * f][1] = r[1];
                kb[2 * f + 1][0] = r[2]; kb[2 * f + 1][1] = r[3];
            }
#pragma unroll
            for (int j = 0; j < 16; j++) mma_(sacc[j], qa[kt], kb[j]);
        }

        if (jt == qt) {   // causal mask on diagonal tile
#pragma unroll
            for (int j = 0; j < 16; j++)
#pragma unroll
                for (int x = 0; x < 4; x++) {
                    int col = j * 8 + i2 + (x & 1);
                    int row = wid * 16 + g + ((x >> 1) << 3);
                    if (col > row) sacc[j][x] = -1e30f;
                }
        }

        // online softmax (2 rows per thread: g and g+8)
        float mx0 = -1e30f, mx1 = -1e30f;
#pragma unroll
        for (int j = 0; j < 16; j++) {
            mx0 = fmaxf(mx0, fmaxf(sacc[j][0], sacc[j][1]));
            mx1 = fmaxf(mx1, fmaxf(sacc[j][2], sacc[j][3]));
        }
        mx0 = fmaxf(mx0, __shfl_xor_sync(0xffffffffu, mx0, 1));
        mx0 = fmaxf(mx0, __shfl_xor_sync(0xffffffffu, mx0, 2));
        mx1 = fmaxf(mx1, __shfl_xor_sync(0xffffffffu, mx1, 1));
        mx1 = fmaxf(mx1, __shfl_xor_sync(0xffffffffu, mx1, 2));
        float mn0 = fmaxf(m0r, mx0), mn1 = fmaxf(m1r, mx1);
        float a0 = ex2((m0r - mn0) * cs), a1 = ex2((m1r - mn1) * cs);
        m0r = mn0; m1r = mn1;
        l0 *= a0; l1 *= a1;
#pragma unroll
        for (int j = 0; j < 8; j++) {
            oacc[j][0] *= a0; oacc[j][1] *= a0;
            oacc[j][2] *= a1; oacc[j][3] *= a1;
        }

        uint32_t Pa[8][4];
        float s0 = 0.0f, s1 = 0.0f;
#pragma unroll
        for (int kk = 0; kk < 8; kk++) {
            float p00 = ex2((sacc[2 * kk][0] - mn0) * cs);
            float p01 = ex2((sacc[2 * kk][1] - mn0) * cs);
            float p02 = ex2((sacc[2 * kk][2] - mn1) * cs);
            float p03 = ex2((sacc[2 * kk][3] - mn1) * cs);
            float p10 = ex2((sacc[2 * kk + 1][0] - mn0) * cs);
            float p11 = ex2((sacc[2 * kk + 1][1] - mn0) * cs);
            float p12 = ex2((sacc[2 * kk + 1][2] - mn1) * cs);
            float p13 = ex2((sacc[2 * kk + 1][3] - mn1) * cs);
            s0 += p00 + p01 + p10 + p11;
            s1 += p02 + p03 + p12 + p13;
            Pa[kk][0] = packh2(p00, p01);
            Pa[kk][1] = packh2(p02, p03);
            Pa[kk][2] = packh2(p10, p11);
            Pa[kk][3] = packh2(p12, p13);
        }
        l0 += s0; l1 += s1;

        // O += P V   (V fragments via ldmatrix.trans)
#pragma unroll
        for (int kk = 0; kk < 8; kk++) {
            uint32_t vb[8][2];
#pragma unroll
            for (int f = 0; f < 4; f++) {
                int krow = kk * 16 + (lane & 7) + ((lane >> 3) & 1) * 8;
                int dcol = f * 16 + ((lane >> 4) & 1) * 8;
                uint32_t r[4];
                ldsm4t(r, Vb + swz((krow << 7) + dcol * 2));
                vb[2 * f][0] = r[0]; vb[2 * f][1] = r[1];
                vb[2 * f + 1][0] = r[2]; vb[2 * f + 1][1] = r[3];
            }
#pragma unroll
            for (int j = 0; j < 8; j++) mma_(oacc[j], Pa[kk], vb[j]);
        }
        __syncthreads();
    }

    // final row-sum reduce and write (hi/lo fp16 for the out-projection)
    l0 += __shfl_xor_sync(0xffffffffu, l0, 1);
    l0 += __shfl_xor_sync(0xffffffffu, l0, 2);
    l1 += __shfl_xor_sync(0xffffffffu, l1, 1);
    l1 += __shfl_xor_sync(0xffffffffu, l1, 2);
    float inv0 = 1.0f / l0, inv1 = 1.0f / l1;

    int tok0 = b * SEQ + qt * 128 + wid * 16 + g;
#pragma unroll
    for (int j = 0; j < 8; j++) {
        int col = h * 64 + j * 8 + i2;
        float v0 = oacc[j][0] * inv0, v1 = oacc[j][1] * inv0;
        float v2 = oacc[j][2] * inv1, v3 = oacc[j][3] * inv1;
        __half h0 = __float2half_rn(v0), h1 = __float2half_rn(v1);
        __half h2 = __float2half_rn(v2), h3 = __float2half_rn(v3);
        *(__half2*)&g_aoh[(size_t)tok0 * D_MODEL + col] = __half2(h0, h1);
        *(__half2*)&g_aol[(size_t)tok0 * D_MODEL + col] =
            __half2(__float2half_rn(v0 - __half2float(h0)),
                    __float2half_rn(v1 - __half2float(h1)));
        *(__half2*)&g_aoh[(size_t)(tok0 + 8) * D_MODEL + col] = __half2(h2, h3);
        *(__half2*)&g_aol[(size_t)(tok0 + 8) * D_MODEL + col] =
            __half2(__float2half_rn(v2 - __half2float(h2)),
                    __float2half_rn(v3 - __half2float(h3)));
    }
}

// ---------------------------------------------------------------------------
extern "C" void kernel_launch(void* const* d_in, const int* in_sizes, int n_in,
                              void* d_out, int out_size)
{
    (void)in_sizes; (void)n_in; (void)out_size;
    const float* x      = (const float*)d_in[0];
    const float* w_qkv  = (const float*)d_in[1];
    const float* w_o    = (const float*)d_in[2];
    const int*   pos    = (const int*)d_in[3];
    float*       out    = (float*)d_out;

    __half *qkvh, *xh, *xl, *wqh, *wql, *woh, *wol, *aoh, *aol;
    cudaGetSymbolAddress((void**)&qkvh, g_qkvh);
    cudaGetSymbolAddress((void**)&xh,  g_xh);
    cudaGetSymbolAddress((void**)&xl,  g_xl);
    cudaGetSymbolAddress((void**)&wqh, g_wqh);
    cudaGetSymbolAddress((void**)&wql, g_wql);
    cudaGetSymbolAddress((void**)&woh, g_woh);
    cudaGetSymbolAddress((void**)&wol, g_wol);
    cudaGetSymbolAddress((void**)&aoh, g_aoh);
    cudaGetSymbolAddress((void**)&aol, g_aol);

    cudaFuncSetAttribute(gemm_tc<true>,
                         cudaFuncAttributeMaxDynamicSharedMemorySize, 2 * STAGE);
    cudaFuncSetAttribute(gemm_tc<false>,
                         cudaFuncAttributeMaxDynamicSharedMemorySize, 2 * STAGE);
    cudaFuncSetAttribute(flash_attn_tc,
                         cudaFuncAttributeMaxDynamicSharedMemorySize, 81920);

    rope_table_kernel<<<SEQ * 32 / 256, 256>>>(pos);

    split_kernel<<<TOKENS * D_MODEL / 4 / 256, 256>>>(x, xh, xl, TOKENS * D_MODEL / 4);
    split_kernel<<<3 * D_MODEL * D_MODEL / 4 / 256, 256>>>(w_qkv, wqh, wql,
                                                           3 * D_MODEL * D_MODEL / 4);
    split_kernel<<<D_MODEL * D_MODEL / 4 / 256, 256>>>(w_o, woh, wol,
                                                       D_MODEL * D_MODEL / 4);

    // QKV projection -> fp16 qkv
    gemm_tc<true><<<dim3(3 * D_MODEL / 128, TOKENS / 128), 256, 2 * STAGE>>>(
        xh, xl, wqh, wql, qkvh, 3 * D_MODEL);

    rope_split_kernel<<<TOKENS * NUM_HEADS * 32 / 256, 256>>>();

    flash_attn_tc<<<dim3(SEQ / 128, NUM_HEADS, BATCH), 256, 81920>>>();

    // output projection -> fp32 out
    gemm_tc<false><<<dim3(D_MODEL / 128, TOKENS / 128), 256, 2 * STAGE>>>(
        aoh, aol, woh, wol, out, D_MODEL);
}

// round 5
// speedup vs baseline: 4.6563x; 1.2428x over previous
#include <cuda_runtime.h>
#include <cuda_fp16.h>
#include <math.h>
#include <stdint.h>

#define D_MODEL   1024
#define NUM_HEADS 16
#define HEAD_DIM  64
#define BATCH     2
#define SEQ       2048
#define TOKENS    (BATCH * SEQ)      // 4096

// ---------------- scratch (device globals; no allocation allowed) ----------
__device__ __align__(16) __half g_qkvh[TOKENS * 3 * D_MODEL];   // fp16 qkv
__device__ __align__(16) __half g_qh[TOKENS * D_MODEL];         // [b,h,s,d]
__device__ __align__(16) __half g_kh[TOKENS * D_MODEL];
__device__ __align__(16) __half g_vh[TOKENS * D_MODEL];
__device__ __align__(16) float  g_ct[SEQ * 32];
__device__ __align__(16) float  g_st[SEQ * 32];
__device__ __align__(16) __half g_xh[TOKENS * D_MODEL];
__device__ __align__(16) __half g_wqh[3 * D_MODEL * D_MODEL];
__device__ __align__(16) __half g_wql[3 * D_MODEL * D_MODEL];
__device__ __align__(16) __half g_woh[D_MODEL * D_MODEL];
__device__ __align__(16) __half g_wol[D_MODEL * D_MODEL];
__device__ __align__(16) __half g_aoh[TOKENS * D_MODEL];

// ---------------------------------------------------------------------------
// helpers
// ---------------------------------------------------------------------------
__device__ __forceinline__ uint32_t smem_u32(const void* p) {
    uint32_t a;
    asm("{ .reg .u64 t; cvta.to.shared.u64 t, %1; cvt.u32.u64 %0, t; }" : "=r"(a) : "l"(p));
    return a;
}
__device__ __forceinline__ void cp16(uint32_t dst, const void* src) {
    asm volatile("cp.async.cg.shared.global [%0], [%1], 16;" :: "r"(dst), "l"(src));
}
#define CP_COMMIT() asm volatile("cp.async.commit_group;")
#define CP_WAIT(n)  asm volatile("cp.async.wait_group %0;" :: "n"(n))

__device__ __forceinline__ void ldsm4(uint32_t* r, uint32_t a) {
    asm volatile("ldmatrix.sync.aligned.m8n8.x4.shared.b16 {%0,%1,%2,%3}, [%4];"
                 : "=r"(r[0]), "=r"(r[1]), "=r"(r[2]), "=r"(r[3]) : "r"(a));
}
__device__ __forceinline__ void ldsm4t(uint32_t* r, uint32_t a) {
    asm volatile("ldmatrix.sync.aligned.m8n8.x4.trans.shared.b16 {%0,%1,%2,%3}, [%4];"
                 : "=r"(r[0]), "=r"(r[1]), "=r"(r[2]), "=r"(r[3]) : "r"(a));
}
__device__ __forceinline__ void mma_(float* c, const uint32_t* a, const uint32_t* b) {
    asm volatile(
        "mma.sync.aligned.m16n8k16.row.col.f32.f16.f16.f32 "
        "{%0,%1,%2,%3}, {%4,%5,%6,%7}, {%8,%9}, {%0,%1,%2,%3};"
        : "+f"(c[0]), "+f"(c[1]), "+f"(c[2]), "+f"(c[3])
        : "r"(a[0]), "r"(a[1]), "r"(a[2]), "r"(a[3]), "r"(b[0]), "r"(b[1]));
}
__device__ __forceinline__ uint32_t swz(uint32_t o) { return o ^ ((o >> 3) & 0x70); }
__device__ __forceinline__ float ex2(float x) {
    float r; asm("ex2.approx.ftz.f32 %0, %1;" : "=f"(r) : "f"(x)); return r;
}
__device__ __forceinline__ uint32_t packh2(float a, float b) {
    __half2 h = __floats2half2_rn(a, b);
    return *(uint32_t*)&h;
}

// ---------------------------------------------------------------------------
// fp32 -> (fp16 hi, fp16 lo) split  (weights)
// ---------------------------------------------------------------------------
__global__ __launch_bounds__(256) void split_kernel(
    const float* __restrict__ in, __half* __restrict__ hi,
    __half* __restrict__ lo, int n4)
{
    int i = blockIdx.x * 256 + threadIdx.x;
    if (i >= n4) return;
    float4 v = ((const float4*)in)[i];
    __half hx = __float2half_rn(v.x), hy = __float2half_rn(v.y);
    __half hz = __float2half_rn(v.z), hw = __float2half_rn(v.w);
    __half2* h2 = (__half2*)hi;
    __half2* l2 = (__half2*)lo;
    h2[2 * i]     = __half2(hx, hy);
    h2[2 * i + 1] = __half2(hz, hw);
    l2[2 * i]     = __half2(__float2half_rn(v.x - __half2float(hx)),
                            __float2half_rn(v.y - __half2float(hy)));
    l2[2 * i + 1] = __half2(__float2half_rn(v.z - __half2float(hz)),
                            __float2half_rn(v.w - __half2float(hw)));
}

// fp32 -> fp16 (activations, hi only)
__global__ __launch_bounds__(256) void tofp16_kernel(
    const float* __restrict__ in, __half* __restrict__ hi, int n4)
{
    int i = blockIdx.x * 256 + threadIdx.x;
    if (i >= n4) return;
    float4 v = ((const float4*)in)[i];
    __half2* h2 = (__half2*)hi;
    h2[2 * i]     = __floats2half2_rn(v.x, v.y);
    h2[2 * i + 1] = __floats2half2_rn(v.z, v.w);
}

// ---------------------------------------------------------------------------
// HMMA 2-term NT GEMM: C[M,N] = A[M,K] (Bh+Bl)[N,K]^T, K=1024, fp32 accum.
// 128x128 tile, BK=64, 8 warps (32x64 warp tile), 3-stage cp.async pipeline.
// Term-outermost MMA order: 16 independent MMAs between accumulator reuse.
// ---------------------------------------------------------------------------
#define GK 1024
#define STAGE 49152   // A 16K | Bh 16K | Bl 16K
#define NSTG  3

__device__ __forceinline__ void gemm_load_stage(
    uint32_t base, int tid, int m0, int n0, int c0,
    const __half* A, const __half* Bh, const __half* Bl)
{
#pragma unroll
    for (int u = 0; u < 4; u++) {
        int idx = u * 256 + tid;          // 0..1023
        int row = idx >> 3, seg = idx & 7;
        uint32_t d = swz((row << 7) + (seg << 4));
        size_t ao = (size_t)(m0 + row) * GK + c0 + seg * 8;
        size_t bo = (size_t)(n0 + row) * GK + c0 + seg * 8;
        cp16(base + d,         A  + ao);
        cp16(base + 16384 + d, Bh + bo);
        cp16(base + 32768 + d, Bl + bo);
    }
}

template<bool HOUT>
__global__ __launch_bounds__(256, 1) void gemm_tc(
    const __half* __restrict__ A,
    const __half* __restrict__ Bh, const __half* __restrict__ Bl,
    void* __restrict__ Cout, int N)
{
    extern __shared__ char smraw[];
    const uint32_t sb = smem_u32(smraw);
    const int tid = threadIdx.x;
    const int wid = tid >> 5, lane = tid & 31;
    const int wm = wid & 3, wn = wid >> 2;
    const int m0 = blockIdx.y << 7, n0 = blockIdx.x << 7;

    float acc[2][8][4];
#pragma unroll
    for (int f = 0; f < 2; f++)
#pragma unroll
        for (int j = 0; j < 8; j++)
#pragma unroll
            for (int x = 0; x < 4; x++) acc[f][j][x] = 0.0f;

    gemm_load_stage(sb, tid, m0, n0, 0, A, Bh, Bl);
    CP_COMMIT();
    gemm_load_stage(sb + STAGE, tid, m0, n0, 64, A, Bh, Bl);
    CP_COMMIT();

    for (int c = 0; c < 16; c++) {
        if (c < 15) CP_WAIT(1); else CP_WAIT(0);
        __syncthreads();                       // stage c ready; c-1 fully consumed
        if (c + 2 < 16) {
            gemm_load_stage(sb + ((c + 2) % NSTG) * STAGE, tid, m0, n0,
                            (c + 2) * 64, A, Bh, Bl);
            CP_COMMIT();
        }
        const uint32_t base = sb + (c % NSTG) * STAGE;

#pragma unroll
        for (int kt = 0; kt < 4; kt++) {
            uint32_t ah[2][4];
#pragma unroll
            for (int f = 0; f < 2; f++) {
                int mrow = wm * 32 + f * 16 + (lane & 7) + ((lane >> 3) & 1) * 8;
                ldsm4(ah[f], base + swz((mrow << 7) + kt * 32 + ((lane >> 4) << 4)));
            }
            uint32_t bh[8][2], bl[8][2];
#pragma unroll
            for (int f = 0; f < 4; f++) {
                int nrow = wn * 64 + f * 16 + (lane & 7) + ((lane >> 4) & 1) * 8;
                uint32_t bd = base + 16384 +
                              swz((nrow << 7) + kt * 32 + (((lane >> 3) & 1) << 4));
                uint32_t r[4];
                ldsm4(r, bd);
                bh[2 * f][0] = r[0]; bh[2 * f][1] = r[1];
                bh[2 * f + 1][0] = r[2]; bh[2 * f + 1][1] = r[3];
                ldsm4(r, bd + 16384);
                bl[2 * f][0] = r[0]; bl[2 * f][1] = r[1];
                bl[2 * f + 1][0] = r[2]; bl[2 * f + 1][1] = r[3];
            }
            // term-outermost: same accumulator reused at distance 16
#pragma unroll
            for (int f = 0; f < 2; f++)
#pragma unroll
                for (int j = 0; j < 8; j++) mma_(acc[f][j], ah[f], bh[j]);
#pragma unroll
            for (int f = 0; f < 2; f++)
#pragma unroll
                for (int j = 0; j < 8; j++) mma_(acc[f][j], ah[f], bl[j]);
        }
    }

    // epilogue
    const int g = lane >> 2, i2 = (lane & 3) * 2;
#pragma unroll
    for (int f = 0; f < 2; f++)
#pragma unroll
        for (int j = 0; j < 8; j++) {
            int row = m0 + wm * 32 + f * 16 + g;
            int col = n0 + wn * 64 + j * 8 + i2;
            if (HOUT) {
                __half* C = (__half*)Cout;
                *(__half2*)&C[(size_t)row * N + col] =
                    __floats2half2_rn(acc[f][j][0], acc[f][j][1]);
                *(__half2*)&C[(size_t)(row + 8) * N + col] =
                    __floats2half2_rn(acc[f][j][2], acc[f][j][3]);
            } else {
                float* C = (float*)Cout;
                *(float2*)&C[(size_t)row * N + col] =
                    make_float2(acc[f][j][0], acc[f][j][1]);
                *(float2*)&C[(size_t)(row + 8) * N + col] =
                    make_float2(acc[f][j][2], acc[f][j][3]);
            }
        }
}

// ---------------------------------------------------------------------------
// RoPE tables (fp64 trig)
// ---------------------------------------------------------------------------
__global__ void rope_table_kernel(const int* __restrict__ pos)
{
    int idx = blockIdx.x * 256 + threadIdx.x;
    if (idx >= SEQ * 32) return;
    int s = idx >> 5, i = idx & 31;
    double f = (double)pos[s] * pow(10000.0, -(double)i / 32.0);
    g_ct[idx] = (float)cos(f);
    g_st[idx] = (float)sin(f);
}

// Split fp16 QKV, apply RoPE to Q/K (fp32 math), transpose to [B,H,S,hd] fp16
__global__ __launch_bounds__(256) void rope_split_kernel()
{
    int idx = blockIdx.x * 256 + threadIdx.x;   // TOKENS*16*32
    int i = idx & 31;
    int h = (idx >> 5) & 15;
    int t = idx >> 9;
    int s = t & (SEQ - 1);
    int b = t >> 11;

    const __half2* base = (const __half2*)(g_qkvh + (size_t)t * 3 * D_MODEL);
    float2 q2 = __half22float2(base[(h * 64 + 2 * i) >> 1]);
    float2 k2 = __half22float2(base[(D_MODEL + h * 64 + 2 * i) >> 1]);
    __half2 v2 = base[(2 * D_MODEL + h * 64 + 2 * i) >> 1];

    float c  = g_ct[s * 32 + i];
    float sn = g_st[s * 32 + i];
    float2 qo = make_float2(q2.x * c - q2.y * sn, q2.y * c + q2.x * sn);
    float2 ko = make_float2(k2.x * c - k2.y * sn, k2.y * c + k2.x * sn);

    size_t off = ((((size_t)b * NUM_HEADS + h) * SEQ + s) * HEAD_DIM + 2 * i) >> 1;
    ((__half2*)g_qh)[off] = __floats2half2_rn(qo.x, qo.y);
    ((__half2*)g_kh)[off] = __floats2half2_rn(ko.x, ko.y);
    ((__half2*)g_vh)[off] = v2;
}

// ---------------------------------------------------------------------------
// Flash attention (causal) with HMMA. Block = 128 q rows of one (b,h).
// 8 warps, warp = 16 q rows. K-chunk = 128 keys, cp.async double buffered.
// smem: Q @0 (16K) | K stages @16384 (2x16K) | V stages @49152 (2x16K)
// ---------------------------------------------------------------------------
__device__ __forceinline__ void flash_load_kv(
    uint32_t sb, int tid, int buf, const __half* K0, const __half* V0)
{
#pragma unroll
    for (int u = 0; u < 4; u++) {
        int idx = u * 256 + tid;
        int row = idx >> 3, seg = idx & 7;
        uint32_t d = swz((row << 7) + (seg << 4));
        cp16(sb + 16384 + buf * 16384 + d, K0 + row * 64 + seg * 8);
        cp16(sb + 49152 + buf * 16384 + d, V0 + row * 64 + seg * 8);
    }
}

__global__ __launch_bounds__(256, 1) void flash_attn_tc()
{
    extern __shared__ char smraw[];
    const uint32_t sb = smem_u32(smraw);
    const int tid = threadIdx.x;
    const int wid = tid >> 5, lane = tid & 31;
    const int qt = (int)gridDim.x - 1 - (int)blockIdx.x;   // heavy tiles first
    const int h = blockIdx.y, b = blockIdx.z;

    const size_t bh = ((size_t)b * NUM_HEADS + h) * SEQ * HEAD_DIM;
    const __half* Qg = g_qh + bh + (size_t)qt * 128 * 64;
    const __half* Kg = g_kh + bh;
    const __half* Vg = g_vh + bh;

    // Q tile load
#pragma unroll
    for (int u = 0; u < 4; u++) {
        int idx = u * 256 + tid;
        int row = idx >> 3, seg = idx & 7;
        cp16(sb + swz((row << 7) + (seg << 4)), Qg + row * 64 + seg * 8);
    }
    CP_COMMIT();
    flash_load_kv(sb, tid, 0, Kg, Vg);
    CP_COMMIT();
    CP_WAIT(1);               // Q ready
    __syncthreads();

    // hoist Q fragments
    uint32_t qa[4][4];
#pragma unroll
    for (int kt = 0; kt < 4; kt++) {
        int mrow = wid * 16 + (lane & 7) + ((lane >> 3) & 1) * 8;
        ldsm4(qa[kt], sb + swz((mrow << 7) + kt * 32 + ((lane >> 4) << 4)));
    }

    float oacc[8][4];
#pragma unroll
    for (int j = 0; j < 8; j++)
#pragma unroll
        for (int x = 0; x < 4; x++) oacc[j][x] = 0.0f;
    float m0r = -1e30f, m1r = -1e30f, l0 = 0.0f, l1 = 0.0f;
    const float cs = 0.125f * 1.44269504f;   // scale * log2(e)
    const int g = lane >> 2, i2 = (lane & 3) * 2;

    for (int jt = 0; jt <= qt; jt++) {
        const int buf = jt & 1;
        if (jt < qt) {
            flash_load_kv(sb, tid, buf ^ 1,
                          Kg + (size_t)(jt + 1) * 128 * 64,
                          Vg + (size_t)(jt + 1) * 128 * 64);
            CP_COMMIT();
            CP_WAIT(1);
        } else {
            CP_WAIT(0);
        }
        __syncthreads();
        const uint32_t Kb = sb + 16384 + buf * 16384;
        const uint32_t Vb = sb + 49152 + buf * 16384;

        // S = Q K^T  (m16 x n128 per warp)
        float sacc[16][4];
#pragma unroll
        for (int j = 0; j < 16; j++)
#pragma unroll
            for (int x = 0; x < 4; x++) sacc[j][x] = 0.0f;

#pragma unroll
        for (int kt = 0; kt < 4; kt++) {
            uint32_t kb[16][2];
#pragma unroll
            for (int f = 0; f < 8; f++) {
                int nrow = f * 16 + (lane & 7) + ((lane >> 4) & 1) * 8;
                uint32_t bd = Kb + swz((nrow << 7) + kt * 32 + (((lane >> 3) & 1) << 4));
                uint32_t r[4];
                ldsm4(r, bd);
                kb[2 * f][0] = r[0]; kb[2 * f][1] = r[1];
                kb[2 * f + 1][0] = r[2]; kb[2 * f + 1][1] = r[3];
            }
#pragma unroll
            for (int j = 0; j < 16; j++) mma_(sacc[j], qa[kt], kb[j]);
        }

        if (jt == qt) {   // causal mask on diagonal tile
#pragma unroll
            for (int j = 0; j < 16; j++)
#pragma unroll
                for (int x = 0; x < 4; x++) {
                    int col = j * 8 + i2 + (x & 1);
                    int row = wid * 16 + g + ((x >> 1) << 3);
                    if (col > row) sacc[j][x] = -1e30f;
                }
        }

        // online softmax (2 rows per thread: g and g+8)
        float mx0 = -1e30f, mx1 = -1e30f;
#pragma unroll
        for (int j = 0; j < 16; j++) {
            mx0 = fmaxf(mx0, fmaxf(sacc[j][0], sacc[j][1]));
            mx1 = fmaxf(mx1, fmaxf(sacc[j][2], sacc[j][3]));
        }
        mx0 = fmaxf(mx0, __shfl_xor_sync(0xffffffffu, mx0, 1));
        mx0 = fmaxf(mx0, __shfl_xor_sync(0xffffffffu, mx0, 2));
        mx1 = fmaxf(mx1, __shfl_xor_sync(0xffffffffu, mx1, 1));
        mx1 = fmaxf(mx1, __shfl_xor_sync(0xffffffffu, mx1, 2));
        float mn0 = fmaxf(m0r, mx0), mn1 = fmaxf(m1r, mx1);
        float a0 = ex2((m0r - mn0) * cs), a1 = ex2((m1r - mn1) * cs);
        m0r = mn0; m1r = mn1;
        l0 *= a0; l1 *= a1;
#pragma unroll
        for (int j = 0; j < 8; j++) {
            oacc[j][0] *= a0; oacc[j][1] *= a0;
            oacc[j][2] *= a1; oacc[j][3] *= a1;
        }

        uint32_t Pa[8][4];
        float s0 = 0.0f, s1 = 0.0f;
#pragma unroll
        for (int kk = 0; kk < 8; kk++) {
            float p00 = ex2((sacc[2 * kk][0] - mn0) * cs);
            float p01 = ex2((sacc[2 * kk][1] - mn0) * cs);
            float p02 = ex2((sacc[2 * kk][2] - mn1) * cs);
            float p03 = ex2((sacc[2 * kk][3] - mn1) * cs);
            float p10 = ex2((sacc[2 * kk + 1][0] - mn0) * cs);
            float p11 = ex2((sacc[2 * kk + 1][1] - mn0) * cs);
            float p12 = ex2((sacc[2 * kk + 1][2] - mn1) * cs);
            float p13 = ex2((sacc[2 * kk + 1][3] - mn1) * cs);
            s0 += p00 + p01 + p10 + p11;
            s1 += p02 + p03 + p12 + p13;
            Pa[kk][0] = packh2(p00, p01);
            Pa[kk][1] = packh2(p02, p03);
            Pa[kk][2] = packh2(p10, p11);
            Pa[kk][3] = packh2(p12, p13);
        }
        l0 += s0; l1 += s1;

        // O += P V   (V fragments via ldmatrix.trans)
#pragma unroll
        for (int kk = 0; kk < 8; kk++) {
            uint32_t vb[8][2];
#pragma unroll
            for (int f = 0; f < 4; f++) {
                int krow = kk * 16 + (lane & 7) + ((lane >> 3) & 1) * 8;
                int dcol = f * 16 + ((lane >> 4) & 1) * 8;
                uint32_t r[4];
                ldsm4t(r, Vb + swz((krow << 7) + dcol * 2));
                vb[2 * f][0] = r[0]; vb[2 * f][1] = r[1];
                vb[2 * f + 1][0] = r[2]; vb[2 * f + 1][1] = r[3];
            }
#pragma unroll
            for (int j = 0; j < 8; j++) mma_(oacc[j], Pa[kk], vb[j]);
        }
        __syncthreads();
    }

    // final row-sum reduce and write (fp16, feeds the out-projection)
    l0 += __shfl_xor_sync(0xffffffffu, l0, 1);
    l0 += __shfl_xor_sync(0xffffffffu, l0, 2);
    l1 += __shfl_xor_sync(0xffffffffu, l1, 1);
    l1 += __shfl_xor_sync(0xffffffffu, l1, 2);
    float inv0 = 1.0f / l0, inv1 = 1.0f / l1;

    int tok0 = b * SEQ + qt * 128 + wid * 16 + g;
#pragma unroll
    for (int j = 0; j < 8; j++) {
        int col = h * 64 + j * 8 + i2;
        *(__half2*)&g_aoh[(size_t)tok0 * D_MODEL + col] =
            __floats2half2_rn(oacc[j][0] * inv0, oacc[j][1] * inv0);
        *(__half2*)&g_aoh[(size_t)(tok0 + 8) * D_MODEL + col] =
            __floats2half2_rn(oacc[j][2] * inv1, oacc[j][3] * inv1);
    }
}

// ---------------------------------------------------------------------------
extern "C" void kernel_launch(void* const* d_in, const int* in_sizes, int n_in,
                              void* d_out, int out_size)
{
    (void)in_sizes; (void)n_in; (void)out_size;
    const float* x      = (const float*)d_in[0];
    const float* w_qkv  = (const float*)d_in[1];
    const float* w_o    = (const float*)d_in[2];
    const int*   pos    = (const int*)d_in[3];
    float*       out    = (float*)d_out;

    __half *qkvh, *xh, *wqh, *wql, *woh, *wol, *aoh;
    cudaGetSymbolAddress((void**)&qkvh, g_qkvh);
    cudaGetSymbolAddress((void**)&xh,  g_xh);
    cudaGetSymbolAddress((void**)&wqh, g_wqh);
    cudaGetSymbolAddress((void**)&wql, g_wql);
    cudaGetSymbolAddress((void**)&woh, g_woh);
    cudaGetSymbolAddress((void**)&wol, g_wol);
    cudaGetSymbolAddress((void**)&aoh, g_aoh);

    cudaFuncSetAttribute(gemm_tc<true>,
                         cudaFuncAttributeMaxDynamicSharedMemorySize, NSTG * STAGE);
    cudaFuncSetAttribute(gemm_tc<false>,
                         cudaFuncAttributeMaxDynamicSharedMemorySize, NSTG * STAGE);
    cudaFuncSetAttribute(flash_attn_tc,
                         cudaFuncAttributeMaxDynamicSharedMemorySize, 81920);

    rope_table_kernel<<<SEQ * 32 / 256, 256>>>(pos);

    tofp16_kernel<<<TOKENS * D_MODEL / 4 / 256, 256>>>(x, xh, TOKENS * D_MODEL / 4);
    split_kernel<<<3 * D_MODEL * D_MODEL / 4 / 256, 256>>>(w_qkv, wqh, wql,
                                                           3 * D_MODEL * D_MODEL / 4);
    split_kernel<<<D_MODEL * D_MODEL / 4 / 256, 256>>>(w_o, woh, wol,
                                                       D_MODEL * D_MODEL / 4);

    // QKV projection -> fp16 qkv
    gemm_tc<true><<<dim3(3 * D_MODEL / 128, TOKENS / 128), 256, NSTG * STAGE>>>(
        xh, wqh, wql, qkvh, 3 * D_MODEL);

    rope_split_kernel<<<TOKENS * NUM_HEADS * 32 / 256, 256>>>();

    flash_attn_tc<<<dim3(SEQ / 128, NUM_HEADS, BATCH), 256, 81920>>>();

    // output projection -> fp32 out
    gemm_tc<false><<<dim3(D_MODEL / 128, TOKENS / 128), 256, NSTG * STAGE>>>(
        aoh, woh, wol, out, D_MODEL);
}

// round 6
// speedup vs baseline: 6.1157x; 1.3134x over previous
#include <cuda_runtime.h>
#include <cuda_fp16.h>
#include <math.h>
#include <stdint.h>

#define D_MODEL   1024
#define NUM_HEADS 16
#define HEAD_DIM  64
#define BATCH     2
#define SEQ       2048
#define TOKENS    (BATCH * SEQ)      // 4096

// ---------------- scratch (device globals; no allocation allowed) ----------
__device__ __align__(16) __half g_qkvh[TOKENS * 3 * D_MODEL];   // fp16 qkv
__device__ __align__(16) __half g_qh[TOKENS * D_MODEL];         // [b,h,s,d], pre-scaled
__device__ __align__(16) __half g_kh[TOKENS * D_MODEL];
__device__ __align__(16) __half g_vh[TOKENS * D_MODEL];
__device__ __align__(16) float  g_ct[SEQ * 32];
__device__ __align__(16) float  g_st[SEQ * 32];
__device__ __align__(16) __half g_xh[TOKENS * D_MODEL];
__device__ __align__(16) __half g_wqh[3 * D_MODEL * D_MODEL];
__device__ __align__(16) __half g_woh[D_MODEL * D_MODEL];
__device__ __align__(16) __half g_aoh[TOKENS * D_MODEL];

// ---------------------------------------------------------------------------
// helpers
// ---------------------------------------------------------------------------
__device__ __forceinline__ uint32_t smem_u32(const void* p) {
    uint32_t a;
    asm("{ .reg .u64 t; cvta.to.shared.u64 t, %1; cvt.u32.u64 %0, t; }" : "=r"(a) : "l"(p));
    return a;
}
__device__ __forceinline__ void cp16(uint32_t dst, const void* src) {
    asm volatile("cp.async.cg.shared.global [%0], [%1], 16;" :: "r"(dst), "l"(src));
}
#define CP_COMMIT() asm volatile("cp.async.commit_group;")
#define CP_WAIT(n)  asm volatile("cp.async.wait_group %0;" :: "n"(n))

__device__ __forceinline__ void ldsm4(uint32_t* r, uint32_t a) {
    asm volatile("ldmatrix.sync.aligned.m8n8.x4.shared.b16 {%0,%1,%2,%3}, [%4];"
                 : "=r"(r[0]), "=r"(r[1]), "=r"(r[2]), "=r"(r[3]) : "r"(a));
}
__device__ __forceinline__ void ldsm4t(uint32_t* r, uint32_t a) {
    asm volatile("ldmatrix.sync.aligned.m8n8.x4.trans.shared.b16 {%0,%1,%2,%3}, [%4];"
                 : "=r"(r[0]), "=r"(r[1]), "=r"(r[2]), "=r"(r[3]) : "r"(a));
}
__device__ __forceinline__ void mma_(float* c, const uint32_t* a, const uint32_t* b) {
    asm volatile(
        "mma.sync.aligned.m16n8k16.row.col.f32.f16.f16.f32 "
        "{%0,%1,%2,%3}, {%4,%5,%6,%7}, {%8,%9}, {%0,%1,%2,%3};"
        : "+f"(c[0]), "+f"(c[1]), "+f"(c[2]), "+f"(c[3])
        : "r"(a[0]), "r"(a[1]), "r"(a[2]), "r"(a[3]), "r"(b[0]), "r"(b[1]));
}
__device__ __forceinline__ uint32_t swz(uint32_t o) { return o ^ ((o >> 3) & 0x70); }
__device__ __forceinline__ float ex2(float x) {
    float r; asm("ex2.approx.ftz.f32 %0, %1;" : "=f"(r) : "f"(x)); return r;
}
__device__ __forceinline__ uint32_t packh2(float a, float b) {
    __half2 h = __floats2half2_rn(a, b);
    return *(uint32_t*)&h;
}

// fp32 -> fp16
__global__ __launch_bounds__(256) void tofp16_kernel(
    const float* __restrict__ in, __half* __restrict__ hi, int n4)
{
    int i = blockIdx.x * 256 + threadIdx.x;
    if (i >= n4) return;
    float4 v = ((const float4*)in)[i];
    __half2* h2 = (__half2*)hi;
    h2[2 * i]     = __floats2half2_rn(v.x, v.y);
    h2[2 * i + 1] = __floats2half2_rn(v.z, v.w);
}

// ---------------------------------------------------------------------------
// HMMA fp16 NT GEMM: C[M,N] = A[M,K] B[N,K]^T, K=1024, fp32 accum.
// 128x128 tile, BK=64, 8 warps (32x64 warp tile), 4-stage cp.async pipeline.
// ---------------------------------------------------------------------------
#define GK 1024
#define STAGE 32768   // A 16K | B 16K
#define NSTG  4

__device__ __forceinline__ void gemm_load_stage(
    uint32_t base, int tid, int m0, int n0, int c0,
    const __half* A, const __half* B)
{
#pragma unroll
    for (int u = 0; u < 4; u++) {
        int idx = u * 256 + tid;          // 0..1023
        int row = idx >> 3, seg = idx & 7;
        uint32_t d = swz((row << 7) + (seg << 4));
        cp16(base + d,         A + (size_t)(m0 + row) * GK + c0 + seg * 8);
        cp16(base + 16384 + d, B + (size_t)(n0 + row) * GK + c0 + seg * 8);
    }
}

template<bool HOUT>
__global__ __launch_bounds__(256, 1) void gemm_tc(
    const __half* __restrict__ A, const __half* __restrict__ B,
    void* __restrict__ Cout, int N)
{
    extern __shared__ char smraw[];
    const uint32_t sb = smem_u32(smraw);
    const int tid = threadIdx.x;
    const int wid = tid >> 5, lane = tid & 31;
    const int wm = wid & 3, wn = wid >> 2;
    const int m0 = blockIdx.y << 7, n0 = blockIdx.x << 7;

    float acc[2][8][4];
#pragma unroll
    for (int f = 0; f < 2; f++)
#pragma unroll
        for (int j = 0; j < 8; j++)
#pragma unroll
            for (int x = 0; x < 4; x++) acc[f][j][x] = 0.0f;

#pragma unroll
    for (int p = 0; p < NSTG - 1; p++) {
        gemm_load_stage(sb + p * STAGE, tid, m0, n0, p * 64, A, B);
        CP_COMMIT();
    }

    for (int c = 0; c < 16; c++) {
        if (c < 14) CP_WAIT(2); else CP_WAIT(0);
        __syncthreads();
        if (c + NSTG - 1 < 16) {
            gemm_load_stage(sb + ((c + NSTG - 1) % NSTG) * STAGE, tid, m0, n0,
                            (c + NSTG - 1) * 64, A, B);
            CP_COMMIT();
        }
        const uint32_t base = sb + (c % NSTG) * STAGE;

#pragma unroll
        for (int kt = 0; kt < 4; kt++) {
            uint32_t ah[2][4];
#pragma unroll
            for (int f = 0; f < 2; f++) {
                int mrow = wm * 32 + f * 16 + (lane & 7) + ((lane >> 3) & 1) * 8;
                ldsm4(ah[f], base + swz((mrow << 7) + kt * 32 + ((lane >> 4) << 4)));
            }
            uint32_t bh[8][2];
#pragma unroll
            for (int f = 0; f < 4; f++) {
                int nrow = wn * 64 + f * 16 + (lane & 7) + ((lane >> 4) & 1) * 8;
                uint32_t r[4];
                ldsm4(r, base + 16384 +
                         swz((nrow << 7) + kt * 32 + (((lane >> 3) & 1) << 4)));
                bh[2 * f][0] = r[0]; bh[2 * f][1] = r[1];
                bh[2 * f + 1][0] = r[2]; bh[2 * f + 1][1] = r[3];
            }
#pragma unroll
            for (int f = 0; f < 2; f++)
#pragma unroll
                for (int j = 0; j < 8; j++) mma_(acc[f][j], ah[f], bh[j]);
        }
    }

    // epilogue
    const int g = lane >> 2, i2 = (lane & 3) * 2;
#pragma unroll
    for (int f = 0; f < 2; f++)
#pragma unroll
        for (int j = 0; j < 8; j++) {
            int row = m0 + wm * 32 + f * 16 + g;
            int col = n0 + wn * 64 + j * 8 + i2;
            if (HOUT) {
                __half* C = (__half*)Cout;
                *(__half2*)&C[(size_t)row * N + col] =
                    __floats2half2_rn(acc[f][j][0], acc[f][j][1]);
                *(__half2*)&C[(size_t)(row + 8) * N + col] =
                    __floats2half2_rn(acc[f][j][2], acc[f][j][3]);
            } else {
                float* C = (float*)Cout;
                *(float2*)&C[(size_t)row * N + col] =
                    make_float2(acc[f][j][0], acc[f][j][1]);
                *(float2*)&C[(size_t)(row + 8) * N + col] =
                    make_float2(acc[f][j][2], acc[f][j][3]);
            }
        }
}

// ---------------------------------------------------------------------------
// RoPE tables (fp64 trig)
// ---------------------------------------------------------------------------
__global__ void rope_table_kernel(const int* __restrict__ pos)
{
    int idx = blockIdx.x * 256 + threadIdx.x;
    if (idx >= SEQ * 32) return;
    int s = idx >> 5, i = idx & 31;
    double f = (double)pos[s] * pow(10000.0, -(double)i / 32.0);
    g_ct[idx] = (float)cos(f);
    g_st[idx] = (float)sin(f);
}

// Split fp16 QKV, RoPE on Q/K (fp32 math), transpose to [B,H,S,hd] fp16.
// Q is pre-scaled by 0.125*log2(e) so flash softmax needs no multiply.
#define QSCALE (0.125f * 1.44269504f)
__global__ __launch_bounds__(256) void rope_split_kernel()
{
    int idx = blockIdx.x * 256 + threadIdx.x;   // TOKENS*16*32
    int i = idx & 31;
    int h = (idx >> 5) & 15;
    int t = idx >> 9;
    int s = t & (SEQ - 1);
    int b = t >> 11;

    const __half2* base = (const __half2*)(g_qkvh + (size_t)t * 3 * D_MODEL);
    float2 q2 = __half22float2(base[(h * 64 + 2 * i) >> 1]);
    float2 k2 = __half22float2(base[(D_MODEL + h * 64 + 2 * i) >> 1]);
    __half2 v2 = base[(2 * D_MODEL + h * 64 + 2 * i) >> 1];

    float c  = g_ct[s * 32 + i];
    float sn = g_st[s * 32 + i];
    float2 qo = make_float2((q2.x * c - q2.y * sn) * QSCALE,
                            (q2.y * c + q2.x * sn) * QSCALE);
    float2 ko = make_float2(k2.x * c - k2.y * sn, k2.y * c + k2.x * sn);

    size_t off = ((((size_t)b * NUM_HEADS + h) * SEQ + s) * HEAD_DIM + 2 * i) >> 1;
    ((__half2*)g_qh)[off] = __floats2half2_rn(qo.x, qo.y);
    ((__half2*)g_kh)[off] = __floats2half2_rn(ko.x, ko.y);
    ((__half2*)g_vh)[off] = v2;
}

// ---------------------------------------------------------------------------
// Flash attention (causal) with HMMA. Block = 128 q rows of one (b,h).
// 8 warps, warp = 16 q rows. K-chunk = 128 keys, cp.async double buffered.
// smem: Q @0 (16K) | K stages @16384 (2x16K) | V stages @49152 (2x16K)
// Scores arrive pre-multiplied by scale*log2e (folded into Q).
// ---------------------------------------------------------------------------
__device__ __forceinline__ void flash_load_kv(
    uint32_t sb, int tid, int buf, const __half* K0, const __half* V0)
{
#pragma unroll
    for (int u = 0; u < 4; u++) {
        int idx = u * 256 + tid;
        int row = idx >> 3, seg = idx & 7;
        uint32_t d = swz((row << 7) + (seg << 4));
        cp16(sb + 16384 + buf * 16384 + d, K0 + row * 64 + seg * 8);
        cp16(sb + 49152 + buf * 16384 + d, V0 + row * 64 + seg * 8);
    }
}

__global__ __launch_bounds__(256, 1) void flash_attn_tc()
{
    extern __shared__ char smraw[];
    const uint32_t sb = smem_u32(smraw);
    const int tid = threadIdx.x;
    const int wid = tid >> 5, lane = tid & 31;
    const int qt = (int)gridDim.x - 1 - (int)blockIdx.x;   // heavy tiles first
    const int h = blockIdx.y, b = blockIdx.z;

    const size_t bh = ((size_t)b * NUM_HEADS + h) * SEQ * HEAD_DIM;
    const __half* Qg = g_qh + bh + (size_t)qt * 128 * 64;
    const __half* Kg = g_kh + bh;
    const __half* Vg = g_vh + bh;

    // Q tile load
#pragma unroll
    for (int u = 0; u < 4; u++) {
        int idx = u * 256 + tid;
        int row = idx >> 3, seg = idx & 7;
        cp16(sb + swz((row << 7) + (seg << 4)), Qg + row * 64 + seg * 8);
    }
    CP_COMMIT();
    flash_load_kv(sb, tid, 0, Kg, Vg);
    CP_COMMIT();
    CP_WAIT(1);               // Q ready
    __syncthreads();

    // hoist Q fragments
    uint32_t qa[4][4];
#pragma unroll
    for (int kt = 0; kt < 4; kt++) {
        int mrow = wid * 16 + (lane & 7) + ((lane >> 3) & 1) * 8;
        ldsm4(qa[kt], sb + swz((mrow << 7) + kt * 32 + ((lane >> 4) << 4)));
    }

    float oacc[8][4];
#pragma unroll
    for (int j = 0; j < 8; j++)
#pragma unroll
        for (int x = 0; x < 4; x++) oacc[j][x] = 0.0f;
    float m0r = -1e30f, m1r = -1e30f, l0 = 0.0f, l1 = 0.0f;
    const int g = lane >> 2, i2 = (lane & 3) * 2;

    for (int jt = 0; jt <= qt; jt++) {
        const int buf = jt & 1;
        if (jt < qt) {
            flash_load_kv(sb, tid, buf ^ 1,
                          Kg + (size_t)(jt + 1) * 128 * 64,
                          Vg + (size_t)(jt + 1) * 128 * 64);
            CP_COMMIT();
            CP_WAIT(1);
        } else {
            CP_WAIT(0);
        }
        __syncthreads();
        const uint32_t Kb = sb + 16384 + buf * 16384;
        const uint32_t Vb = sb + 49152 + buf * 16384;

        // S = Q K^T  (m16 x n128 per warp), already in log2-domain units
        float sacc[16][4];
#pragma unroll
        for (int j = 0; j < 16; j++)
#pragma unroll
            for (int x = 0; x < 4; x++) sacc[j][x] = 0.0f;

#pragma unroll
        for (int kt = 0; kt < 4; kt++) {
            uint32_t kb[16][2];
#pragma unroll
            for (int f = 0; f < 8; f++) {
                int nrow = f * 16 + (lane & 7) + ((lane >> 4) & 1) * 8;
                uint32_t r[4];
                ldsm4(r, Kb + swz((nrow << 7) + kt * 32 + (((lane >> 3) & 1) << 4)));
                kb[2 * f][0] = r[0]; kb[2 * f][1] = r[1];
                kb[2 * f + 1][0] = r[2]; kb[2 * f + 1][1] = r[3];
            }
#pragma unroll
            for (int j = 0; j < 16; j++) mma_(sacc[j], qa[kt], kb[j]);
        }

        if (jt == qt) {   // causal mask on diagonal tile
#pragma unroll
            for (int j = 0; j < 16; j++)
#pragma unroll
                for (int x = 0; x < 4; x++) {
                    int col = j * 8 + i2 + (x & 1);
                    int row = wid * 16 + g + ((x >> 1) << 3);
                    if (col > row) sacc[j][x] = -1e30f;
                }
        }

        // online softmax (2 rows per thread: g and g+8)
        float mx0 = -1e30f, mx1 = -1e30f;
#pragma unroll
        for (int j = 0; j < 16; j++) {
            mx0 = fmaxf(mx0, fmaxf(sacc[j][0], sacc[j][1]));
            mx1 = fmaxf(mx1, fmaxf(sacc[j][2], sacc[j][3]));
        }
        mx0 = fmaxf(mx0, __shfl_xor_sync(0xffffffffu, mx0, 1));
        mx0 = fmaxf(mx0, __shfl_xor_sync(0xffffffffu, mx0, 2));
        mx1 = fmaxf(mx1, __shfl_xor_sync(0xffffffffu, mx1, 1));
        mx1 = fmaxf(mx1, __shfl_xor_sync(0xffffffffu, mx1, 2));
        float mn0 = fmaxf(m0r, mx0), mn1 = fmaxf(m1r, mx1);
        float a0 = ex2(m0r - mn0), a1 = ex2(m1r - mn1);
        m0r = mn0; m1r = mn1;
        l0 *= a0; l1 *= a1;
#pragma unroll
        for (int j = 0; j < 8; j++) {
            oacc[j][0] *= a0; oacc[j][1] *= a0;
            oacc[j][2] *= a1; oacc[j][3] *= a1;
        }

        uint32_t Pa[8][4];
        float s0 = 0.0f, s1 = 0.0f;
#pragma unroll
        for (int kk = 0; kk < 8; kk++) {
            float p00 = ex2(sacc[2 * kk][0] - mn0);
            float p01 = ex2(sacc[2 * kk][1] - mn0);
            float p02 = ex2(sacc[2 * kk][2] - mn1);
            float p03 = ex2(sacc[2 * kk][3] - mn1);
            float p10 = ex2(sacc[2 * kk + 1][0] - mn0);
            float p11 = ex2(sacc[2 * kk + 1][1] - mn0);
            float p12 = ex2(sacc[2 * kk + 1][2] - mn1);
            float p13 = ex2(sacc[2 * kk + 1][3] - mn1);
            s0 += p00 + p01 + p10 + p11;
            s1 += p02 + p03 + p12 + p13;
            Pa[kk][0] = packh2(p00, p01);
            Pa[kk][1] = packh2(p02, p03);
            Pa[kk][2] = packh2(p10, p11);
            Pa[kk][3] = packh2(p12, p13);
        }
        l0 += s0; l1 += s1;

        // O += P V   (V fragments via ldmatrix.trans)
#pragma unroll
        for (int kk = 0; kk < 8; kk++) {
            uint32_t vb[8][2];
#pragma unroll
            for (int f = 0; f < 4; f++) {
                int krow = kk * 16 + (lane & 7) + ((lane >> 3) & 1) * 8;
                int dcol = f * 16 + ((lane >> 4) & 1) * 8;
                uint32_t r[4];
                ldsm4t(r, Vb + swz((krow << 7) + dcol * 2));
                vb[2 * f][0] = r[0]; vb[2 * f][1] = r[1];
                vb[2 * f + 1][0] = r[2]; vb[2 * f + 1][1] = r[3];
            }
#pragma unroll
            for (int j = 0; j < 8; j++) mma_(oacc[j], Pa[kk], vb[j]);
        }
        __syncthreads();
    }

    // final row-sum reduce and write (fp16, feeds the out-projection)
    l0 += __shfl_xor_sync(0xffffffffu, l0, 1);
    l0 += __shfl_xor_sync(0xffffffffu, l0, 2);
    l1 += __shfl_xor_sync(0xffffffffu, l1, 1);
    l1 += __shfl_xor_sync(0xffffffffu, l1, 2);
    float inv0 = 1.0f / l0, inv1 = 1.0f / l1;

    int tok0 = b * SEQ + qt * 128 + wid * 16 + g;
#pragma unroll
    for (int j = 0; j < 8; j++) {
        int col = h * 64 + j * 8 + i2;
        *(__half2*)&g_aoh[(size_t)tok0 * D_MODEL + col] =
            __floats2half2_rn(oacc[j][0] * inv0, oacc[j][1] * inv0);
        *(__half2*)&g_aoh[(size_t)(tok0 + 8) * D_MODEL + col] =
            __floats2half2_rn(oacc[j][2] * inv1, oacc[j][3] * inv1);
    }
}

// ---------------------------------------------------------------------------
extern "C" void kernel_launch(void* const* d_in, const int* in_sizes, int n_in,
                              void* d_out, int out_size)
{
    (void)in_sizes; (void)n_in; (void)out_size;
    const float* x      = (const float*)d_in[0];
    const float* w_qkv  = (const float*)d_in[1];
    const float* w_o    = (const float*)d_in[2];
    const int*   pos    = (const int*)d_in[3];
    float*       out    = (float*)d_out;

    __half *qkvh, *xh, *wqh, *woh, *aoh;
    cudaGetSymbolAddress((void**)&qkvh, g_qkvh);
    cudaGetSymbolAddress((void**)&xh,  g_xh);
    cudaGetSymbolAddress((void**)&wqh, g_wqh);
    cudaGetSymbolAddress((void**)&woh, g_woh);
    cudaGetSymbolAddress((void**)&aoh, g_aoh);

    cudaFuncSetAttribute(gemm_tc<true>,
                         cudaFuncAttributeMaxDynamicSharedMemorySize, NSTG * STAGE);
    cudaFuncSetAttribute(gemm_tc<false>,
                         cudaFuncAttributeMaxDynamicSharedMemorySize, NSTG * STAGE);
    cudaFuncSetAttribute(flash_attn_tc,
                         cudaFuncAttributeMaxDynamicSharedMemorySize, 81920);

    rope_table_kernel<<<SEQ * 32 / 256, 256>>>(pos);

    tofp16_kernel<<<TOKENS * D_MODEL / 4 / 256, 256>>>(x, xh, TOKENS * D_MODEL / 4);
    tofp16_kernel<<<3 * D_MODEL * D_MODEL / 4 / 256, 256>>>(w_qkv, wqh,
                                                            3 * D_MODEL * D_MODEL / 4);
    tofp16_kernel<<<D_MODEL * D_MODEL / 4 / 256, 256>>>(w_o, woh,
                                                        D_MODEL * D_MODEL / 4);

    // QKV projection -> fp16 qkv
    gemm_tc<true><<<dim3(3 * D_MODEL / 128, TOKENS / 128), 256, NSTG * STAGE>>>(
        xh, wqh, qkvh, 3 * D_MODEL);

    rope_split_kernel<<<TOKENS * NUM_HEADS * 32 / 256, 256>>>();

    flash_attn_tc<<<dim3(SEQ / 128, NUM_HEADS, BATCH), 256, 81920>>>();

    // output projection -> fp32 out
    gemm_tc<false><<<dim3(D_MODEL / 128, TOKENS / 128), 256, NSTG * STAGE>>>(
        aoh, woh, out, D_MODEL);
}

// round 10
// speedup vs baseline: 6.2311x; 1.0189x over previous
#include <cuda_runtime.h>
#include <cuda_fp16.h>
#include <math.h>
#include <stdint.h>

#define D_MODEL   1024
#define NUM_HEADS 16
#define HEAD_DIM  64
#define BATCH     2
#define SEQ       2048
#define TOKENS    (BATCH * SEQ)      // 4096
#define QSCALE    (0.125f * 1.44269504f)

// ---------------- scratch (device globals; no allocation allowed) ----------
__device__ __align__(16) __half g_qh[TOKENS * D_MODEL];   // [b,h,s,d], pre-scaled
__device__ __align__(16) __half g_kh[TOKENS * D_MODEL];
__device__ __align__(16) __half g_vh[TOKENS * D_MODEL];
__device__ __align__(16) float  g_ct[SEQ * 32];
__device__ __align__(16) float  g_st[SEQ * 32];
__device__ __align__(16) __half g_xh[TOKENS * D_MODEL];
__device__ __align__(16) __half g_wqh[3 * D_MODEL * D_MODEL];
__device__ __align__(16) __half g_woh[D_MODEL * D_MODEL];
__device__ __align__(16) __half g_aoh[TOKENS * D_MODEL];

// ---------------------------------------------------------------------------
// helpers
// ---------------------------------------------------------------------------
__device__ __forceinline__ uint32_t smem_u32(const void* p) {
    uint32_t a;
    asm("{ .reg .u64 t; cvta.to.shared.u64 t, %1; cvt.u32.u64 %0, t; }" : "=r"(a) : "l"(p));
    return a;
}
__device__ __forceinline__ void cp16(uint32_t dst, const void* src) {
    asm volatile("cp.async.cg.shared.global [%0], [%1], 16;" :: "r"(dst), "l"(src));
}
#define CP_COMMIT() asm volatile("cp.async.commit_group;")
#define CP_WAIT(n)  asm volatile("cp.async.wait_group %0;" :: "n"(n))

__device__ __forceinline__ void ldsm4(uint32_t* r, uint32_t a) {
    asm volatile("ldmatrix.sync.aligned.m8n8.x4.shared.b16 {%0,%1,%2,%3}, [%4];"
                 : "=r"(r[0]), "=r"(r[1]), "=r"(r[2]), "=r"(r[3]) : "r"(a));
}
__device__ __forceinline__ void ldsm4t(uint32_t* r, uint32_t a) {
    asm volatile("ldmatrix.sync.aligned.m8n8.x4.trans.shared.b16 {%0,%1,%2,%3}, [%4];"
                 : "=r"(r[0]), "=r"(r[1]), "=r"(r[2]), "=r"(r[3]) : "r"(a));
}
__device__ __forceinline__ void mma_(float* c, const uint32_t* a, const uint32_t* b) {
    asm volatile(
        "mma.sync.aligned.m16n8k16.row.col.f32.f16.f16.f32 "
        "{%0,%1,%2,%3}, {%4,%5,%6,%7}, {%8,%9}, {%0,%1,%2,%3};"
        : "+f"(c[0]), "+f"(c[1]), "+f"(c[2]), "+f"(c[3])
        : "r"(a[0]), "r"(a[1]), "r"(a[2]), "r"(a[3]), "r"(b[0]), "r"(b[1]));
}
__device__ __forceinline__ uint32_t swz(uint32_t o) { return o ^ ((o >> 3) & 0x70); }
__device__ __forceinline__ float ex2(float x) {
    float r; asm("ex2.approx.ftz.f32 %0, %1;" : "=f"(r) : "f"(x)); return r;
}
__device__ __forceinline__ __half2 h2ex2(__half2 x) {
    uint32_t xi = *(uint32_t*)&x, ri;
    asm("ex2.approx.f16x2 %0, %1;" : "=r"(ri) : "r"(xi));
    return *(__half2*)&ri;
}
__device__ __forceinline__ uint32_t h2u(__half2 h) { return *(uint32_t*)&h; }

// fp32 -> fp16
__global__ __launch_bounds__(256) void tofp16_kernel(
    const float* __restrict__ in, __half* __restrict__ hi, int n4)
{
    int i = blockIdx.x * 256 + threadIdx.x;
    if (i >= n4) return;
    float4 v = ((const float4*)in)[i];
    __half2* h2 = (__half2*)hi;
    h2[2 * i]     = __floats2half2_rn(v.x, v.y);
    h2[2 * i + 1] = __floats2half2_rn(v.z, v.w);
}

// ---------------------------------------------------------------------------
// RoPE tables (fp64 trig)
// ---------------------------------------------------------------------------
__global__ void rope_table_kernel(const int* __restrict__ pos)
{
    int idx = blockIdx.x * 256 + threadIdx.x;
    if (idx >= SEQ * 32) return;
    int s = idx >> 5, i = idx & 31;
    double f = (double)pos[s] * pow(10000.0, -(double)i / 32.0);
    g_ct[idx] = (float)cos(f);
    g_st[idx] = (float)sin(f);
}

// ---------------------------------------------------------------------------
// HMMA fp16 NT GEMM: C[M,N] = A[M,K] B[N,K]^T, K=1024, fp32 accum.
// 128x128 tile, BK=64, 8 warps (32x64 warp tile), 4-stage cp.async pipeline.
// MODE 0: fp32 C output. MODE 1: fused RoPE+split epilogue -> g_qh/g_kh/g_vh.
// ---------------------------------------------------------------------------
#define GK 1024
#define STAGE 32768   // A 16K | B 16K
#define NSTG  4

__device__ __forceinline__ void gemm_load_stage(
    uint32_t base, int tid, int m0, int n0, int c0,
    const __half* A, const __half* B)
{
#pragma unroll
    for (int u = 0; u < 4; u++) {
        int idx = u * 256 + tid;          // 0..1023
        int row = idx >> 3, seg = idx & 7;
        uint32_t d = swz((row << 7) + (seg << 4));
        cp16(base + d,         A + (size_t)(m0 + row) * GK + c0 + seg * 8);
        cp16(base + 16384 + d, B + (size_t)(n0 + row) * GK + c0 + seg * 8);
    }
}

template<int MODE>
__global__ __launch_bounds__(256, 1) void gemm_tc(
    const __half* __restrict__ A, const __half* __restrict__ B,
    float* __restrict__ Cout, int N)
{
    extern __shared__ char smraw[];
    const uint32_t sb = smem_u32(smraw);
    const int tid = threadIdx.x;
    const int wid = tid >> 5, lane = tid & 31;
    const int wm = wid & 3, wn = wid >> 2;
    const int m0 = blockIdx.y << 7, n0 = blockIdx.x << 7;

    float acc[2][8][4];
#pragma unroll
    for (int f = 0; f < 2; f++)
#pragma unroll
        for (int j = 0; j < 8; j++)
#pragma unroll
            for (int x = 0; x < 4; x++) acc[f][j][x] = 0.0f;

#pragma unroll
    for (int p = 0; p < NSTG - 1; p++) {
        gemm_load_stage(sb + p * STAGE, tid, m0, n0, p * 64, A, B);
        CP_COMMIT();
    }

    for (int c = 0; c < 16; c++) {
        if (c < 14) CP_WAIT(2); else CP_WAIT(0);
        __syncthreads();
        if (c + NSTG - 1 < 16) {
            gemm_load_stage(sb + ((c + NSTG - 1) % NSTG) * STAGE, tid, m0, n0,
                            (c + NSTG - 1) * 64, A, B);
            CP_COMMIT();
        }
        const uint32_t base = sb + (c % NSTG) * STAGE;

#pragma unroll
        for (int kt = 0; kt < 4; kt++) {
            uint32_t ah[2][4];
#pragma unroll
            for (int f = 0; f < 2; f++) {
                int mrow = wm * 32 + f * 16 + (lane & 7) + ((lane >> 3) & 1) * 8;
                ldsm4(ah[f], base + swz((mrow << 7) + kt * 32 + ((lane >> 4) << 4)));
            }
            uint32_t bh[8][2];
#pragma unroll
            for (int f = 0; f < 4; f++) {
                int nrow = wn * 64 + f * 16 + (lane & 7) + ((lane >> 4) & 1) * 8;
                uint32_t r[4];
                ldsm4(r, base + 16384 +
                         swz((nrow << 7) + kt * 32 + (((lane >> 3) & 1) << 4)));
                bh[2 * f][0] = r[0]; bh[2 * f][1] = r[1];
                bh[2 * f + 1][0] = r[2]; bh[2 * f + 1][1] = r[3];
            }
#pragma unroll
            for (int f = 0; f < 2; f++)
#pragma unroll
                for (int j = 0; j < 8; j++) mma_(acc[f][j], ah[f], bh[j]);
        }
    }

    const int g = lane >> 2, i2 = (lane & 3) * 2;

    if (MODE == 0) {
#pragma unroll
        for (int f = 0; f < 2; f++)
#pragma unroll
            for (int j = 0; j < 8; j++) {
                int row = m0 + wm * 32 + f * 16 + g;
                int col = n0 + wn * 64 + j * 8 + i2;
                *(float2*)&Cout[(size_t)row * N + col] =
                    make_float2(acc[f][j][0], acc[f][j][1]);
                *(float2*)&Cout[(size_t)(row + 8) * N + col] =
                    make_float2(acc[f][j][2], acc[f][j][3]);
            }
    } else {
        // fused RoPE + head-split + transpose epilogue.
        // i2 is even => (acc[..][0], acc[..][1]) is an (even,odd) RoPE pair.
        const int sel  = n0 >> 10;               // 0=q, 1=k, 2=v
        const int csec = (n0 & 1023) + wn * 64;
#pragma unroll
        for (int f = 0; f < 2; f++) {
            int row = m0 + wm * 32 + f * 16 + g;     // token for rows [0..1]
            int s = row & (SEQ - 1), b = row >> 11;
#pragma unroll
            for (int j = 0; j < 8; j++) {
                int col = csec + j * 8 + i2;
                int hh = col >> 6, d = col & 63, ii = d >> 1;
                size_t o1 = ((((size_t)b * NUM_HEADS + hh) * SEQ + s) * HEAD_DIM + d) >> 1;
                size_t o2 = o1 + 8 * HEAD_DIM / 2;   // token row+8
                float e0 = acc[f][j][0], od0 = acc[f][j][1];
                float e1 = acc[f][j][2], od1 = acc[f][j][3];
                if (sel == 2) {
                    ((__half2*)g_vh)[o1] = __floats2half2_rn(e0, od0);
                    ((__half2*)g_vh)[o2] = __floats2half2_rn(e1, od1);
                } else {
                    float c0 = g_ct[s * 32 + ii],       sn0 = g_st[s * 32 + ii];
                    float c1 = g_ct[(s + 8) * 32 + ii], sn1 = g_st[(s + 8) * 32 + ii];
                    float re0 = e0 * c0 - od0 * sn0, ro0 = od0 * c0 + e0 * sn0;
                    float re1 = e1 * c1 - od1 * sn1, ro1 = od1 * c1 + e1 * sn1;
                    if (sel == 0) {
                        ((__half2*)g_qh)[o1] =
                            __floats2half2_rn(re0 * QSCALE, ro0 * QSCALE);
                        ((__half2*)g_qh)[o2] =
                            __floats2half2_rn(re1 * QSCALE, ro1 * QSCALE);
                    } else {
                        ((__half2*)g_kh)[o1] = __floats2half2_rn(re0, ro0);
                        ((__half2*)g_kh)[o2] = __floats2half2_rn(re1, ro1);
                    }
                }
            }
        }
    }
}

// ---------------------------------------------------------------------------
// Flash attention (causal) with HMMA. Block = 128 q rows of one (b,h).
// 8 warps, warp = 16 q rows. K-chunk = 128 keys, 3-stage cp.async pipeline.
// smem: Q @0 (16K) | 3 x (K 16K + V 16K) @16384.  Scores pre-scaled via Q.
// ---------------------------------------------------------------------------
#define FSMEM (16384 + 3 * 32768)   // 114688

__device__ __forceinline__ void flash_load_kv(
    uint32_t sb, int tid, int buf, const __half* K0, const __half* V0)
{
    const uint32_t kbase = sb + 16384 + buf * 32768;
#pragma unroll
    for (int u = 0; u < 4; u++) {
        int idx = u * 256 + tid;
        int row = idx >> 3, seg = idx & 7;
        uint32_t d = swz((row << 7) + (seg << 4));
        cp16(kbase + d,         K0 + row * 64 + seg * 8);
        cp16(kbase + 16384 + d, V0 + row * 64 + seg * 8);
    }
}

__global__ __launch_bounds__(256, 1) void flash_attn_tc()
{
    extern __shared__ char smraw[];
    const uint32_t sb = smem_u32(smraw);
    const int tid = threadIdx.x;
    const int wid = tid >> 5, lane = tid & 31;
    const int qt = (int)gridDim.x - 1 - (int)blockIdx.x;   // heavy tiles first
    const int h = blockIdx.y, b = blockIdx.z;

    const size_t bh = ((size_t)b * NUM_HEADS + h) * SEQ * HEAD_DIM;
    const __half* Qg = g_qh + bh + (size_t)qt * 128 * 64;
    const __half* Kg = g_kh + bh;
    const __half* Vg = g_vh + bh;

    // Q tile load
#pragma unroll
    for (int u = 0; u < 4; u++) {
        int idx = u * 256 + tid;
        int row = idx >> 3, seg = idx & 7;
        cp16(sb + swz((row << 7) + (seg << 4)), Qg + row * 64 + seg * 8);
    }
    CP_COMMIT();
    flash_load_kv(sb, tid, 0, Kg, Vg);
    CP_COMMIT();
    if (qt >= 1) {
        flash_load_kv(sb, tid, 1, Kg + 128 * 64, Vg + 128 * 64);
        CP_COMMIT();
        CP_WAIT(2);           // Q done
    } else {
        CP_WAIT(1);           // Q done
    }
    __syncthreads();

    // hoist Q fragments
    uint32_t qa[4][4];
#pragma unroll
    for (int kt = 0; kt < 4; kt++) {
        int mrow = wid * 16 + (lane & 7) + ((lane >> 3) & 1) * 8;
        ldsm4(qa[kt], sb + swz((mrow << 7) + kt * 32 + ((lane >> 4) << 4)));
    }

    float oacc[8][4];
#pragma unroll
    for (int j = 0; j < 8; j++)
#pragma unroll
        for (int x = 0; x < 4; x++) oacc[j][x] = 0.0f;
    float m0r = -1e30f, m1r = -1e30f, l0 = 0.0f, l1 = 0.0f;
    const int g = lane >> 2, i2 = (lane & 3) * 2;

    for (int jt = 0; jt <= qt; jt++) {
        const int buf = jt % 3;
        if (jt + 2 <= qt) {
            flash_load_kv(sb, tid, (jt + 2) % 3,
                          Kg + (size_t)(jt + 2) * 128 * 64,
                          Vg + (size_t)(jt + 2) * 128 * 64);
            CP_COMMIT();
            CP_WAIT(2);
        } else if (jt + 1 <= qt) {
            CP_WAIT(1);
        } else {
            CP_WAIT(0);
        }
        __syncthreads();
        const uint32_t Kb = sb + 16384 + buf * 32768;
        const uint32_t Vb = Kb + 16384;

        // S = Q K^T  (m16 x n128 per warp), log2-domain units
        float sacc[16][4];
#pragma unroll
        for (int j = 0; j < 16; j++)
#pragma unroll
            for (int x = 0; x < 4; x++) sacc[j][x] = 0.0f;

#pragma unroll
        for (int kt = 0; kt < 4; kt++) {
            uint32_t kb[16][2];
#pragma unroll
            for (int f = 0; f < 8; f++) {
                int nrow = f * 16 + (lane & 7) + ((lane >> 4) & 1) * 8;
                uint32_t r[4];
                ldsm4(r, Kb + swz((nrow << 7) + kt * 32 + (((lane >> 3) & 1) << 4)));
                kb[2 * f][0] = r[0]; kb[2 * f][1] = r[1];
                kb[2 * f + 1][0] = r[2]; kb[2 * f + 1][1] = r[3];
            }
#pragma unroll
            for (int j = 0; j < 16; j++) mma_(sacc[j], qa[kt], kb[j]);
        }

        if (jt == qt) {   // causal mask on diagonal tile
#pragma unroll
            for (int j = 0; j < 16; j++)
#pragma unroll
                for (int x = 0; x < 4; x++) {
                    int col = j * 8 + i2 + (x & 1);
                    int row = wid * 16 + g + ((x >> 1) << 3);
                    if (col > row) sacc[j][x] = -1e30f;
                }
        }

        // pack to half2: sp0 = row g pairs, sp1 = row g+8 pairs
        __half2 sp0[16], sp1[16];
#pragma unroll
        for (int j = 0; j < 16; j++) {
            sp0[j] = __floats2half2_rn(sacc[j][0], sacc[j][1]);
            sp1[j] = __floats2half2_rn(sacc[j][2], sacc[j][3]);
        }
        // max via HMAX2 tree
        __half2 mh0 = sp0[0], mh1 = sp1[0];
#pragma unroll
        for (int j = 1; j < 16; j++) {
            mh0 = __hmax2(mh0, sp0[j]);
            mh1 = __hmax2(mh1, sp1[j]);
        }
        float mx0 = fmaxf(__low2float(mh0), __high2float(mh0));
        float mx1 = fmaxf(__low2float(mh1), __high2float(mh1));
        mx0 = fmaxf(mx0, __shfl_xor_sync(0xffffffffu, mx0, 1));
        mx0 = fmaxf(mx0, __shfl_xor_sync(0xffffffffu, mx0, 2));
        mx1 = fmaxf(mx1, __shfl_xor_sync(0xffffffffu, mx1, 1));
        mx1 = fmaxf(mx1, __shfl_xor_sync(0xffffffffu, mx1, 2));
        float mn0 = fmaxf(m0r, mx0), mn1 = fmaxf(m1r, mx1);
        float a0 = ex2(m0r - mn0), a1 = ex2(m1r - mn1);
        m0r = mn0; m1r = mn1;
        l0 *= a0; l1 *= a1;
#pragma unroll
        for (int j = 0; j < 8; j++) {
            oacc[j][0] *= a0; oacc[j][1] *= a0;
            oacc[j][2] *= a1; oacc[j][3] *= a1;
        }

        // exp in f16x2; MUFU output doubles as the P fragment
        const __half2 mn0h = __float2half2_rn(mn0);
        const __half2 mn1h = __float2half2_rn(mn1);
        uint32_t Pa[8][4];
        float s0 = 0.0f, s1 = 0.0f;
#pragma unroll
        for (int kk = 0; kk < 8; kk++) {
            __half2 p00 = h2ex2(__hsub2(sp0[2 * kk],     mn0h));
            __half2 p10 = h2ex2(__hsub2(sp0[2 * kk + 1], mn0h));
            __half2 p01 = h2ex2(__hsub2(sp1[2 * kk],     mn1h));
            __half2 p11 = h2ex2(__hsub2(sp1[2 * kk + 1], mn1h));
            Pa[kk][0] = h2u(p00); Pa[kk][1] = h2u(p01);
            Pa[kk][2] = h2u(p10); Pa[kk][3] = h2u(p11);
            float2 f0 = __half22float2(__hadd2(p00, p10));
            float2 f1 = __half22float2(__hadd2(p01, p11));
            s0 += f0.x + f0.y;
            s1 += f1.x + f1.y;
        }
        l0 += s0; l1 += s1;

        // O += P V   (V fragments via ldmatrix.trans)
#pragma unroll
        for (int kk = 0; kk < 8; kk++) {
            uint32_t vb[8][2];
#pragma unroll
            for (int f = 0; f < 4; f++) {
                int krow = kk * 16 + (lane & 7) + ((lane >> 3) & 1) * 8;
                int dcol = f * 16 + ((lane >> 4) & 1) * 8;
                uint32_t r[4];
                ldsm4t(r, Vb + swz((krow << 7) + dcol * 2));
                vb[2 * f][0] = r[0]; vb[2 * f][1] = r[1];
                vb[2 * f + 1][0] = r[2]; vb[2 * f + 1][1] = r[3];
            }
#pragma unroll
            for (int j = 0; j < 8; j++) mma_(oacc[j], Pa[kk], vb[j]);
        }
        __syncthreads();
    }

    // final row-sum reduce and write (fp16, feeds the out-projection)
    l0 += __shfl_xor_sync(0xffffffffu, l0, 1);
    l0 += __shfl_xor_sync(0xffffffffu, l0, 2);
    l1 += __shfl_xor_sync(0xffffffffu, l1, 1);
    l1 += __shfl_xor_sync(0xffffffffu, l1, 2);
    float inv0 = 1.0f / l0, inv1 = 1.0f / l1;

    int tok0 = b * SEQ + qt * 128 + wid * 16 + g;
#pragma unroll
    for (int j = 0; j < 8; j++) {
        int col = h * 64 + j * 8 + i2;
        *(__half2*)&g_aoh[(size_t)tok0 * D_MODEL + col] =
            __floats2half2_rn(oacc[j][0] * inv0, oacc[j][1] * inv0);
        *(__half2*)&g_aoh[(size_t)(tok0 + 8) * D_MODEL + col] =
            __floats2half2_rn(oacc[j][2] * inv1, oacc[j][3] * inv1);
    }
}

// ---------------------------------------------------------------------------
extern "C" void kernel_launch(void* const* d_in, const int* in_sizes, int n_in,
                              void* d_out, int out_size)
{
    (void)in_sizes; (void)n_in; (void)out_size;
    const float* x      = (const float*)d_in[0];
    const float* w_qkv  = (const float*)d_in[1];
    const float* w_o    = (const float*)d_in[2];
    const int*   pos    = (const int*)d_in[3];
    float*       out    = (float*)d_out;

    __half *xh, *wqh, *woh, *aoh;
    cudaGetSymbolAddress((void**)&xh,  g_xh);
    cudaGetSymbolAddress((void**)&wqh, g_wqh);
    cudaGetSymbolAddress((void**)&woh, g_woh);
    cudaGetSymbolAddress((void**)&aoh, g_aoh);

    cudaFuncSetAttribute(gemm_tc<0>,
                         cudaFuncAttributeMaxDynamicSharedMemorySize, NSTG * STAGE);
    cudaFuncSetAttribute(gemm_tc<1>,
                         cudaFuncAttributeMaxDynamicSharedMemorySize, NSTG * STAGE);
    cudaFuncSetAttribute(flash_attn_tc,
                         cudaFuncAttributeMaxDynamicSharedMemorySize, FSMEM);

    rope_table_kernel<<<SEQ * 32 / 256, 256>>>(pos);

    tofp16_kernel<<<TOKENS * D_MODEL / 4 / 256, 256>>>(x, xh, TOKENS * D_MODEL / 4);
    tofp16_kernel<<<3 * D_MODEL * D_MODEL / 4 / 256, 256>>>(w_qkv, wqh,
                                                            3 * D_MODEL * D_MODEL / 4);
    tofp16_kernel<<<D_MODEL * D_MODEL / 4 / 256, 256>>>(w_o, woh,
                                                        D_MODEL * D_MODEL / 4);

    // QKV projection with fused RoPE/split/transpose epilogue
    gemm_tc<1><<<dim3(3 * D_MODEL / 128, TOKENS / 128), 256, NSTG * STAGE>>>(
        xh, wqh, nullptr, 3 * D_MODEL);

    flash_attn_tc<<<dim3(SEQ / 128, NUM_HEADS, BATCH), 256, FSMEM>>>();

    // output projection -> fp32 out
    gemm_tc<0><<<dim3(D_MODEL / 128, TOKENS / 128), 256, NSTG * STAGE>>>(
        aoh, woh, out, D_MODEL);
}

// round 11
// speedup vs baseline: 6.4802x; 1.0400x over previous
#include <cuda_runtime.h>
#include <cuda_fp16.h>
#include <math.h>
#include <stdint.h>

#define D_MODEL   1024
#define NUM_HEADS 16
#define HEAD_DIM  64
#define BATCH     2
#define SEQ       2048
#define TOKENS    (BATCH * SEQ)      // 4096
#define QSCALE    (0.125f * 1.44269504f)

// ---------------- scratch (device globals; no allocation allowed) ----------
__device__ __align__(16) __half g_qh[TOKENS * D_MODEL];   // [b,h,s,d], pre-scaled
__device__ __align__(16) __half g_kh[TOKENS * D_MODEL];
__device__ __align__(16) __half g_vh[TOKENS * D_MODEL];
__device__ __align__(16) float  g_ct[SEQ * 32];
__device__ __align__(16) float  g_st[SEQ * 32];
__device__ __align__(16) __half g_xh[TOKENS * D_MODEL];
__device__ __align__(16) __half g_wqh[3 * D_MODEL * D_MODEL];
__device__ __align__(16) __half g_woh[D_MODEL * D_MODEL];
__device__ __align__(16) __half g_aoh[TOKENS * D_MODEL];

// ---------------------------------------------------------------------------
// helpers
// ---------------------------------------------------------------------------
__device__ __forceinline__ uint32_t smem_u32(const void* p) {
    uint32_t a;
    asm("{ .reg .u64 t; cvta.to.shared.u64 t, %1; cvt.u32.u64 %0, t; }" : "=r"(a) : "l"(p));
    return a;
}
__device__ __forceinline__ void cp16(uint32_t dst, const void* src) {
    asm volatile("cp.async.cg.shared.global [%0], [%1], 16;" :: "r"(dst), "l"(src));
}
#define CP_COMMIT() asm volatile("cp.async.commit_group;")
#define CP_WAIT(n)  asm volatile("cp.async.wait_group %0;" :: "n"(n))

__device__ __forceinline__ void ldsm4(uint32_t* r, uint32_t a) {
    asm volatile("ldmatrix.sync.aligned.m8n8.x4.shared.b16 {%0,%1,%2,%3}, [%4];"
                 : "=r"(r[0]), "=r"(r[1]), "=r"(r[2]), "=r"(r[3]) : "r"(a));
}
__device__ __forceinline__ void ldsm4t(uint32_t* r, uint32_t a) {
    asm volatile("ldmatrix.sync.aligned.m8n8.x4.trans.shared.b16 {%0,%1,%2,%3}, [%4];"
                 : "=r"(r[0]), "=r"(r[1]), "=r"(r[2]), "=r"(r[3]) : "r"(a));
}
__device__ __forceinline__ void mma_(float* c, const uint32_t* a, const uint32_t* b) {
    asm volatile(
        "mma.sync.aligned.m16n8k16.row.col.f32.f16.f16.f32 "
        "{%0,%1,%2,%3}, {%4,%5,%6,%7}, {%8,%9}, {%0,%1,%2,%3};"
        : "+f"(c[0]), "+f"(c[1]), "+f"(c[2]), "+f"(c[3])
        : "r"(a[0]), "r"(a[1]), "r"(a[2]), "r"(a[3]), "r"(b[0]), "r"(b[1]));
}
__device__ __forceinline__ uint32_t swz(uint32_t o) { return o ^ ((o >> 3) & 0x70); }
__device__ __forceinline__ float ex2(float x) {
    float r; asm("ex2.approx.ftz.f32 %0, %1;" : "=f"(r) : "f"(x)); return r;
}
__device__ __forceinline__ __half2 h2ex2(__half2 x) {
    uint32_t xi = *(uint32_t*)&x, ri;
    asm("ex2.approx.f16x2 %0, %1;" : "=r"(ri) : "r"(xi));
    return *(__half2*)&ri;
}
__device__ __forceinline__ uint32_t h2u(__half2 h) { return *(uint32_t*)&h; }

// fp32 -> fp16
__global__ __launch_bounds__(256) void tofp16_kernel(
    const float* __restrict__ in, __half* __restrict__ hi, int n4)
{
    int i = blockIdx.x * 256 + threadIdx.x;
    if (i >= n4) return;
    float4 v = ((const float4*)in)[i];
    __half2* h2 = (__half2*)hi;
    h2[2 * i]     = __floats2half2_rn(v.x, v.y);
    h2[2 * i + 1] = __floats2half2_rn(v.z, v.w);
}

// ---------------------------------------------------------------------------
// RoPE tables (fp64 trig)
// ---------------------------------------------------------------------------
__global__ void rope_table_kernel(const int* __restrict__ pos)
{
    int idx = blockIdx.x * 256 + threadIdx.x;
    if (idx >= SEQ * 32) return;
    int s = idx >> 5, i = idx & 31;
    double f = (double)pos[s] * pow(10000.0, -(double)i / 32.0);
    g_ct[idx] = (float)cos(f);
    g_st[idx] = (float)sin(f);
}

// ---------------------------------------------------------------------------
// HMMA fp16 NT GEMM: C[M,N] = A[M,K] B[N,K]^T, K=1024, fp32 accum.
// 128x128 tile, BK=64, 8 warps (32x64 warp tile), 3-stage cp.async pipeline,
// 2 CTAs/SM. MODE 0: fp32 C out. MODE 1: fused RoPE+split -> g_qh/g_kh/g_vh.
// ---------------------------------------------------------------------------
#define GK 1024
#define STAGE 32768   // A 16K | B 16K
#define NSTG  3

__device__ __forceinline__ void gemm_load_stage(
    uint32_t base, int tid, int m0, int n0, int c0,
    const __half* A, const __half* B)
{
#pragma unroll
    for (int u = 0; u < 4; u++) {
        int idx = u * 256 + tid;          // 0..1023
        int row = idx >> 3, seg = idx & 7;
        uint32_t d = swz((row << 7) + (seg << 4));
        cp16(base + d,         A + (size_t)(m0 + row) * GK + c0 + seg * 8);
        cp16(base + 16384 + d, B + (size_t)(n0 + row) * GK + c0 + seg * 8);
    }
}

template<int MODE>
__global__ __launch_bounds__(256, 2) void gemm_tc(
    const __half* __restrict__ A, const __half* __restrict__ B,
    float* __restrict__ Cout, int N)
{
    extern __shared__ char smraw[];
    const uint32_t sb = smem_u32(smraw);
    const int tid = threadIdx.x;
    const int wid = tid >> 5, lane = tid & 31;
    const int wm = wid & 3, wn = wid >> 2;
    const int m0 = blockIdx.y << 7, n0 = blockIdx.x << 7;

    float acc[2][8][4];
#pragma unroll
    for (int f = 0; f < 2; f++)
#pragma unroll
        for (int j = 0; j < 8; j++)
#pragma unroll
            for (int x = 0; x < 4; x++) acc[f][j][x] = 0.0f;

#pragma unroll
    for (int p = 0; p < NSTG - 1; p++) {
        gemm_load_stage(sb + p * STAGE, tid, m0, n0, p * 64, A, B);
        CP_COMMIT();
    }

    for (int c = 0; c < 16; c++) {
        if (c < 15) CP_WAIT(1); else CP_WAIT(0);
        __syncthreads();
        if (c + NSTG - 1 < 16) {
            gemm_load_stage(sb + ((c + NSTG - 1) % NSTG) * STAGE, tid, m0, n0,
                            (c + NSTG - 1) * 64, A, B);
            CP_COMMIT();
        }
        const uint32_t base = sb + (c % NSTG) * STAGE;

#pragma unroll
        for (int kt = 0; kt < 4; kt++) {
            uint32_t ah[2][4];
#pragma unroll
            for (int f = 0; f < 2; f++) {
                int mrow = wm * 32 + f * 16 + (lane & 7) + ((lane >> 3) & 1) * 8;
                ldsm4(ah[f], base + swz((mrow << 7) + kt * 32 + ((lane >> 4) << 4)));
            }
            uint32_t bh[8][2];
#pragma unroll
            for (int f = 0; f < 4; f++) {
                int nrow = wn * 64 + f * 16 + (lane & 7) + ((lane >> 4) & 1) * 8;
                uint32_t r[4];
                ldsm4(r, base + 16384 +
                         swz((nrow << 7) + kt * 32 + (((lane >> 3) & 1) << 4)));
                bh[2 * f][0] = r[0]; bh[2 * f][1] = r[1];
                bh[2 * f + 1][0] = r[2]; bh[2 * f + 1][1] = r[3];
            }
#pragma unroll
            for (int f = 0; f < 2; f++)
#pragma unroll
                for (int j = 0; j < 8; j++) mma_(acc[f][j], ah[f], bh[j]);
        }
    }

    const int g = lane >> 2, i2 = (lane & 3) * 2;

    if (MODE == 0) {
#pragma unroll
        for (int f = 0; f < 2; f++)
#pragma unroll
            for (int j = 0; j < 8; j++) {
                int row = m0 + wm * 32 + f * 16 + g;
                int col = n0 + wn * 64 + j * 8 + i2;
                *(float2*)&Cout[(size_t)row * N + col] =
                    make_float2(acc[f][j][0], acc[f][j][1]);
                *(float2*)&Cout[(size_t)(row + 8) * N + col] =
                    make_float2(acc[f][j][2], acc[f][j][3]);
            }
    } else {
        // fused RoPE + head-split + transpose epilogue.
        const int sel  = n0 >> 10;               // 0=q, 1=k, 2=v
        const int csec = (n0 & 1023) + wn * 64;
#pragma unroll
        for (int f = 0; f < 2; f++) {
            int row = m0 + wm * 32 + f * 16 + g;     // token
            int s = row & (SEQ - 1), b = row >> 11;
#pragma unroll
            for (int j = 0; j < 8; j++) {
                int col = csec + j * 8 + i2;
                int hh = col >> 6, d = col & 63, ii = d >> 1;
                size_t o1 = ((((size_t)b * NUM_HEADS + hh) * SEQ + s) * HEAD_DIM + d) >> 1;
                size_t o2 = o1 + 8 * HEAD_DIM / 2;   // token row+8
                float e0 = acc[f][j][0], od0 = acc[f][j][1];
                float e1 = acc[f][j][2], od1 = acc[f][j][3];
                if (sel == 2) {
                    ((__half2*)g_vh)[o1] = __floats2half2_rn(e0, od0);
                    ((__half2*)g_vh)[o2] = __floats2half2_rn(e1, od1);
                } else {
                    float c0 = g_ct[s * 32 + ii],       sn0 = g_st[s * 32 + ii];
                    float c1 = g_ct[(s + 8) * 32 + ii], sn1 = g_st[(s + 8) * 32 + ii];
                    float re0 = e0 * c0 - od0 * sn0, ro0 = od0 * c0 + e0 * sn0;
                    float re1 = e1 * c1 - od1 * sn1, ro1 = od1 * c1 + e1 * sn1;
                    if (sel == 0) {
                        ((__half2*)g_qh)[o1] =
                            __floats2half2_rn(re0 * QSCALE, ro0 * QSCALE);
                        ((__half2*)g_qh)[o2] =
                            __floats2half2_rn(re1 * QSCALE, ro1 * QSCALE);
                    } else {
                        ((__half2*)g_kh)[o1] = __floats2half2_rn(re0, ro0);
                        ((__half2*)g_kh)[o2] = __floats2half2_rn(re1, ro1);
                    }
                }
            }
        }
    }
}

// ---------------------------------------------------------------------------
// Flash attention (causal) with HMMA. Block = 128 q rows of one (b,h).
// 8 warps, warp = 16 q rows. K-chunk = 128 keys, 2-stage cp.async pipeline,
// 2 CTAs/SM (80KB smem, <=128 regs). Scores pre-scaled via Q.
// smem: Q @0 (16K) | 2 x (K 16K + V 16K) @16384
// ---------------------------------------------------------------------------
#define FSMEM (16384 + 2 * 32768)   // 81920

__device__ __forceinline__ void flash_load_kv(
    uint32_t sb, int tid, int buf, const __half* K0, const __half* V0)
{
    const uint32_t kbase = sb + 16384 + buf * 32768;
#pragma unroll
    for (int u = 0; u < 4; u++) {
        int idx = u * 256 + tid;
        int row = idx >> 3, seg = idx & 7;
        uint32_t d = swz((row << 7) + (seg << 4));
        cp16(kbase + d,         K0 + row * 64 + seg * 8);
        cp16(kbase + 16384 + d, V0 + row * 64 + seg * 8);
    }
}

__global__ __launch_bounds__(256, 2) void flash_attn_tc()
{
    extern __shared__ char smraw[];
    const uint32_t sb = smem_u32(smraw);
    const int tid = threadIdx.x;
    const int wid = tid >> 5, lane = tid & 31;
    const int qt = (int)gridDim.x - 1 - (int)blockIdx.x;   // heavy tiles first
    const int h = blockIdx.y, b = blockIdx.z;

    const size_t bh = ((size_t)b * NUM_HEADS + h) * SEQ * HEAD_DIM;
    const __half* Qg = g_qh + bh + (size_t)qt * 128 * 64;
    const __half* Kg = g_kh + bh;
    const __half* Vg = g_vh + bh;

    // Q tile load
#pragma unroll
    for (int u = 0; u < 4; u++) {
        int idx = u * 256 + tid;
        int row = idx >> 3, seg = idx & 7;
        cp16(sb + swz((row << 7) + (seg << 4)), Qg + row * 64 + seg * 8);
    }
    CP_COMMIT();
    flash_load_kv(sb, tid, 0, Kg, Vg);
    CP_COMMIT();
    CP_WAIT(1);               // Q ready
    __syncthreads();

    // hoist Q fragments
    uint32_t qa[4][4];
#pragma unroll
    for (int kt = 0; kt < 4; kt++) {
        int mrow = wid * 16 + (lane & 7) + ((lane >> 3) & 1) * 8;
        ldsm4(qa[kt], sb + swz((mrow << 7) + kt * 32 + ((lane >> 4) << 4)));
    }

    float oacc[8][4];
#pragma unroll
    for (int j = 0; j < 8; j++)
#pragma unroll
        for (int x = 0; x < 4; x++) oacc[j][x] = 0.0f;
    float m0r = -1e30f, m1r = -1e30f, l0 = 0.0f, l1 = 0.0f;
    const int g = lane >> 2, i2 = (lane & 3) * 2;

    for (int jt = 0; jt <= qt; jt++) {
        const int buf = jt & 1;
        if (jt < qt) {
            flash_load_kv(sb, tid, buf ^ 1,
                          Kg + (size_t)(jt + 1) * 128 * 64,
                          Vg + (size_t)(jt + 1) * 128 * 64);
            CP_COMMIT();
            CP_WAIT(1);
        } else {
            CP_WAIT(0);
        }
        __syncthreads();
        const uint32_t Kb = sb + 16384 + buf * 32768;
        const uint32_t Vb = Kb + 16384;

        // S = Q K^T  (m16 x n128 per warp), log2-domain units
        float sacc[16][4];
#pragma unroll
        for (int j = 0; j < 16; j++)
#pragma unroll
            for (int x = 0; x < 4; x++) sacc[j][x] = 0.0f;

#pragma unroll
        for (int kt = 0; kt < 4; kt++) {
            uint32_t kb[16][2];
#pragma unroll
            for (int f = 0; f < 8; f++) {
                int nrow = f * 16 + (lane & 7) + ((lane >> 4) & 1) * 8;
                uint32_t r[4];
                ldsm4(r, Kb + swz((nrow << 7) + kt * 32 + (((lane >> 3) & 1) << 4)));
                kb[2 * f][0] = r[0]; kb[2 * f][1] = r[1];
                kb[2 * f + 1][0] = r[2]; kb[2 * f + 1][1] = r[3];
            }
#pragma unroll
            for (int j = 0; j < 16; j++) mma_(sacc[j], qa[kt], kb[j]);
        }

        if (jt == qt) {   // causal mask on diagonal tile
#pragma unroll
            for (int j = 0; j < 16; j++)
#pragma unroll
                for (int x = 0; x < 4; x++) {
                    int col = j * 8 + i2 + (x & 1);
                    int row = wid * 16 + g + ((x >> 1) << 3);
                    if (col > row) sacc[j][x] = -1e30f;
                }
        }

        // fp32 row max (keeps regs low: no packed score arrays)
        float mx0 = -1e30f, mx1 = -1e30f;
#pragma unroll
        for (int j = 0; j < 16; j++) {
            mx0 = fmaxf(mx0, fmaxf(sacc[j][0], sacc[j][1]));
            mx1 = fmaxf(mx1, fmaxf(sacc[j][2], sacc[j][3]));
        }
        mx0 = fmaxf(mx0, __shfl_xor_sync(0xffffffffu, mx0, 1));
        mx0 = fmaxf(mx0, __shfl_xor_sync(0xffffffffu, mx0, 2));
        mx1 = fmaxf(mx1, __shfl_xor_sync(0xffffffffu, mx1, 1));
        mx1 = fmaxf(mx1, __shfl_xor_sync(0xffffffffu, mx1, 2));
        float mn0 = fmaxf(m0r, mx0), mn1 = fmaxf(m1r, mx1);
        float a0 = ex2(m0r - mn0), a1 = ex2(m1r - mn1);
        m0r = mn0; m1r = mn1;
        l0 *= a0; l1 *= a1;
#pragma unroll
        for (int j = 0; j < 8; j++) {
            oacc[j][0] *= a0; oacc[j][1] *= a0;
            oacc[j][2] *= a1; oacc[j][3] *= a1;
        }

        // pack -> hsub -> f16x2 exp; MUFU output doubles as the P fragment
        const __half2 mn0h = __float2half2_rn(mn0);
        const __half2 mn1h = __float2half2_rn(mn1);
        uint32_t Pa[8][4];
        float s0 = 0.0f, s1 = 0.0f;
#pragma unroll
        for (int kk = 0; kk < 8; kk++) {
            __half2 p00 = h2ex2(__hsub2(
                __floats2half2_rn(sacc[2 * kk][0], sacc[2 * kk][1]), mn0h));
            __half2 p10 = h2ex2(__hsub2(
                __floats2half2_rn(sacc[2 * kk + 1][0], sacc[2 * kk + 1][1]), mn0h));
            __half2 p01 = h2ex2(__hsub2(
                __floats2half2_rn(sacc[2 * kk][2], sacc[2 * kk][3]), mn1h));
            __half2 p11 = h2ex2(__hsub2(
                __floats2half2_rn(sacc[2 * kk + 1][2], sacc[2 * kk + 1][3]), mn1h));
            Pa[kk][0] = h2u(p00); Pa[kk][1] = h2u(p01);
            Pa[kk][2] = h2u(p10); Pa[kk][3] = h2u(p11);
            float2 f0 = __half22float2(__hadd2(p00, p10));
            float2 f1 = __half22float2(__hadd2(p01, p11));
            s0 += f0.x + f0.y;
            s1 += f1.x + f1.y;
        }
        l0 += s0; l1 += s1;

        // O += P V   (V fragments via ldmatrix.trans)
#pragma unroll
        for (int kk = 0; kk < 8; kk++) {
            uint32_t vb[8][2];
#pragma unroll
            for (int f = 0; f < 4; f++) {
                int krow = kk * 16 + (lane & 7) + ((lane >> 3) & 1) * 8;
                int dcol = f * 16 + ((lane >> 4) & 1) * 8;
                uint32_t r[4];
                ldsm4t(r, Vb + swz((krow << 7) + dcol * 2));
                vb[2 * f][0] = r[0]; vb[2 * f][1] = r[1];
                vb[2 * f + 1][0] = r[2]; vb[2 * f + 1][1] = r[3];
            }
#pragma unroll
            for (int j = 0; j < 8; j++) mma_(oacc[j], Pa[kk], vb[j]);
        }
        __syncthreads();
    }

    // final row-sum reduce and write (fp16, feeds the out-projection)
    l0 += __shfl_xor_sync(0xffffffffu, l0, 1);
    l0 += __shfl_xor_sync(0xffffffffu, l0, 2);
    l1 += __shfl_xor_sync(0xffffffffu, l1, 1);
    l1 += __shfl_xor_sync(0xffffffffu, l1, 2);
    float inv0 = 1.0f / l0, inv1 = 1.0f / l1;

    int tok0 = b * SEQ + qt * 128 + wid * 16 + g;
#pragma unroll
    for (int j = 0; j < 8; j++) {
        int col = h * 64 + j * 8 + i2;
        *(__half2*)&g_aoh[(size_t)tok0 * D_MODEL + col] =
            __floats2half2_rn(oacc[j][0] * inv0, oacc[j][1] * inv0);
        *(__half2*)&g_aoh[(size_t)(tok0 + 8) * D_MODEL + col] =
            __floats2half2_rn(oacc[j][2] * inv1, oacc[j][3] * inv1);
    }
}

// ---------------------------------------------------------------------------
extern "C" void kernel_launch(void* const* d_in, const int* in_sizes, int n_in,
                              void* d_out, int out_size)
{
    (void)in_sizes; (void)n_in; (void)out_size;
    const float* x      = (const float*)d_in[0];
    const float* w_qkv  = (const float*)d_in[1];
    const float* w_o    = (const float*)d_in[2];
    const int*   pos    = (const int*)d_in[3];
    float*       out    = (float*)d_out;

    __half *xh, *wqh, *woh, *aoh;
    cudaGetSymbolAddress((void**)&xh,  g_xh);
    cudaGetSymbolAddress((void**)&wqh, g_wqh);
    cudaGetSymbolAddress((void**)&woh, g_woh);
    cudaGetSymbolAddress((void**)&aoh, g_aoh);

    cudaFuncSetAttribute(gemm_tc<0>,
                         cudaFuncAttributeMaxDynamicSharedMemorySize, NSTG * STAGE);
    cudaFuncSetAttribute(gemm_tc<1>,
                         cudaFuncAttributeMaxDynamicSharedMemorySize, NSTG * STAGE);
    cudaFuncSetAttribute(flash_attn_tc,
                         cudaFuncAttributeMaxDynamicSharedMemorySize, FSMEM);

    rope_table_kernel<<<SEQ * 32 / 256, 256>>>(pos);

    tofp16_kernel<<<TOKENS * D_MODEL / 4 / 256, 256>>>(x, xh, TOKENS * D_MODEL / 4);
    tofp16_kernel<<<3 * D_MODEL * D_MODEL / 4 / 256, 256>>>(w_qkv, wqh,
                                                            3 * D_MODEL * D_MODEL / 4);
    tofp16_kernel<<<D_MODEL * D_MODEL / 4 / 256, 256>>>(w_o, woh,
                                                        D_MODEL * D_MODEL / 4);

    // QKV projection with fused RoPE/split/transpose epilogue
    gemm_tc<1><<<dim3(3 * D_MODEL / 128, TOKENS / 128), 256, NSTG * STAGE>>>(
        xh, wqh, nullptr, 3 * D_MODEL);

    flash_attn_tc<<<dim3(SEQ / 128, NUM_HEADS, BATCH), 256, FSMEM>>>();

    // output projection -> fp32 out
    gemm_tc<0><<<dim3(D_MODEL / 128, TOKENS / 128), 256, NSTG * STAGE>>>(
        aoh, woh, out, D_MODEL);
}